// round 1
// baseline (speedup 1.0000x reference)
#include <cuda_runtime.h>
#include <math.h>

// ---------------------------------------------------------------------------
// Problem constants
// ---------------------------------------------------------------------------
#define BATCH   4
#define SEQ     2048
#define DEMB    1024
#define NHEADS  16
#define DHEAD   64
#define MROWS   (BATCH * SEQ)        // 8192
#define QKV_N   (3 * DEMB)           // 3072

// Scratch (device globals: allocation-free per harness rules)
__device__ float g_qkv[(size_t)MROWS * QKV_N];   // 96 MB: [m][3*D]  q|k|v
__device__ float g_att[(size_t)MROWS * DEMB];    // 32 MB: attention output (B,S,H,dh)->(m, D)

// ---------------------------------------------------------------------------
// GEMM:  C[M,N] = A[M,K] @ B[N,K]^T + bias[N]      (all fp32, row-major)
// Tile 128x64, bk=16, 256 threads, 8x4 micro-tile.
// M % 128 == 0, N % 64 == 0, K % 16 == 0 (true for both GEMMs here).
// ---------------------------------------------------------------------------
#define GBM 128
#define GBN 64
#define GBK 16

__global__ __launch_bounds__(256)
void gemm_nt_bias(const float* __restrict__ A, const float* __restrict__ B,
                  const float* __restrict__ bias, float* __restrict__ C,
                  int M, int N, int K)
{
    __shared__ float As[GBK][GBM + 1];
    __shared__ float Bs[GBK][GBN + 1];

    const int tid = threadIdx.x;
    const int tx  = tid & 15;         // n-direction (16 groups of 4)
    const int ty  = tid >> 4;         // m-direction (16 groups of 8)
    const int m0  = blockIdx.y * GBM;
    const int n0  = blockIdx.x * GBN;

    const float* Ablk = A + (size_t)m0 * K;
    const float* Bblk = B + (size_t)n0 * K;

    float acc[8][4];
#pragma unroll
    for (int r = 0; r < 8; r++)
#pragma unroll
        for (int c = 0; c < 4; c++) acc[r][c] = 0.f;

    for (int k0 = 0; k0 < K; k0 += GBK) {
        // Load A tile: 128x16 = 2048 elems, 8 per thread, coalesced along k
        const int lk = tid & 15;          // k within tile
        const int lr = tid >> 4;          // row group
#pragma unroll
        for (int i = 0; i < 8; i++) {
            int m = lr + i * 16;
            As[lk][m] = Ablk[(size_t)m * K + k0 + lk];
        }
        // Load B tile: 64x16 = 1024 elems, 4 per thread
#pragma unroll
        for (int i = 0; i < 4; i++) {
            int n = lr + i * 16;
            Bs[lk][n] = Bblk[(size_t)n * K + k0 + lk];
        }
        __syncthreads();

#pragma unroll
        for (int kk = 0; kk < GBK; kk++) {
            float a[8], b[4];
#pragma unroll
            for (int r = 0; r < 8; r++) a[r] = As[kk][ty * 8 + r];
#pragma unroll
            for (int c = 0; c < 4; c++) b[c] = Bs[kk][tx * 4 + c];
#pragma unroll
            for (int r = 0; r < 8; r++)
#pragma unroll
                for (int c = 0; c < 4; c++)
                    acc[r][c] += a[r] * b[c];
        }
        __syncthreads();
    }

#pragma unroll
    for (int r = 0; r < 8; r++) {
        int m = m0 + ty * 8 + r;
#pragma unroll
        for (int c = 0; c < 4; c++) {
            int n = n0 + tx * 4 + c;
            C[(size_t)m * N + n] = acc[r][c] + bias[n];
        }
    }
}

// ---------------------------------------------------------------------------
// Flash attention (fp32, online softmax, causal optional).
// Grid: (SEQ/64, BATCH*NHEADS).  Block: 256 threads.
// q-tile = 64 rows, k-tile = 64 rows, dh = 64.
// Dynamic smem: Qs[64][65] (Q^T: d-major), KVs[64][65] (K^T then V), Ps[64][65],
//               row stats 4x64.
// ---------------------------------------------------------------------------
#define AT_PAD 65

__global__ __launch_bounds__(256)
void attn_kernel(const float* __restrict__ qkv, float* __restrict__ out,
                 const int* __restrict__ causal_flag)
{
    extern __shared__ float sm[];
    float* Qs        = sm;                      // [d][m]: d*65+m
    float* KVs       = Qs  + 64 * AT_PAD;       // K: d*65+n ; later V: k*65+d
    float* Ps        = KVs + 64 * AT_PAD;       // [m][n]: m*65+n
    float* row_m     = Ps  + 64 * AT_PAD;       // running max
    float* row_l     = row_m + 64;              // running sum
    float* row_scale = row_l + 64;              // exp(old_m - new_m)
    float* row_newm  = row_scale + 64;

    const int tid = threadIdx.x;
    const int tx  = tid & 15;                   // 16 groups of 4 (n or d cols)
    const int ty  = tid >> 4;                   // 16 groups of 4 (m rows)
    const int iq  = blockIdx.x;                 // q tile index
    const int bh  = blockIdx.y;
    const int b   = bh >> 4;
    const int h   = bh & 15;
    const int q0  = iq * 64;
    const int causal = *causal_flag;

    const float* base = qkv + (size_t)b * SEQ * QKV_N + h * DHEAD;

    // Load Q tile (transposed into smem)
    for (int idx = tid; idx < 64 * 64; idx += 256) {
        int m = idx >> 6, d = idx & 63;
        Qs[d * AT_PAD + m] = base[(size_t)(q0 + m) * QKV_N + d];
    }
    if (tid < 64) { row_m[tid] = -INFINITY; row_l[tid] = 0.f; }

    float Oacc[4][4];
#pragma unroll
    for (int r = 0; r < 4; r++)
#pragma unroll
        for (int c = 0; c < 4; c++) Oacc[r][c] = 0.f;

    const int ntiles = causal ? (iq + 1) : (SEQ / 64);
    const float scale = 0.125f;                 // 1/sqrt(64)

    for (int jk = 0; jk < ntiles; jk++) {
        const int k0 = jk * 64;
        __syncthreads();   // protect KVs/Ps from previous iteration consumers

        // Load K tile (transposed: [d][n])
        for (int idx = tid; idx < 64 * 64; idx += 256) {
            int n = idx >> 6, d = idx & 63;
            KVs[d * AT_PAD + n] = base[(size_t)(k0 + n) * QKV_N + DEMB + d];
        }
        __syncthreads();

        // S = Q @ K^T  (4x4 micro per thread)
        float s[4][4];
#pragma unroll
        for (int r = 0; r < 4; r++)
#pragma unroll
            for (int c = 0; c < 4; c++) s[r][c] = 0.f;
#pragma unroll
        for (int d = 0; d < 64; d++) {
            float a[4], bb[4];
#pragma unroll
            for (int r = 0; r < 4; r++) a[r]  = Qs [d * AT_PAD + ty * 4 + r];
#pragma unroll
            for (int c = 0; c < 4; c++) bb[c] = KVs[d * AT_PAD + tx * 4 + c];
#pragma unroll
            for (int r = 0; r < 4; r++)
#pragma unroll
                for (int c = 0; c < 4; c++)
                    s[r][c] += a[r] * bb[c];
        }

        // mask + scale, stage raw scores in Ps for row-max
        const bool diag = causal && (jk == iq);
#pragma unroll
        for (int r = 0; r < 4; r++) {
            int m = ty * 4 + r;
#pragma unroll
            for (int c = 0; c < 4; c++) {
                int n = tx * 4 + c;
                float v = s[r][c] * scale;
                if (diag && n > m) v = -INFINITY;
                s[r][c] = v;
                Ps[m * AT_PAD + n] = v;
            }
        }
        __syncthreads();

        // Load V tile into KVs ([k][d]) — safe: S compute done
        for (int idx = tid; idx < 64 * 64; idx += 256) {
            int kr = idx >> 6, d = idx & 63;
            KVs[kr * AT_PAD + d] = base[(size_t)(k0 + kr) * QKV_N + 2 * DEMB + d];
        }
        // Row stats (64 threads, one row each)
        if (tid < 64) {
            float mx = -INFINITY;
#pragma unroll 8
            for (int n = 0; n < 64; n++) mx = fmaxf(mx, Ps[tid * AT_PAD + n]);
            float old = row_m[tid];
            float nm  = fmaxf(old, mx);
            row_newm[tid]  = nm;
            row_scale[tid] = (old == -INFINITY) ? 0.f : __expf(old - nm);
            row_m[tid]     = nm;
        }
        __syncthreads();

        // P = exp(s - new_m); rescale O accumulators
#pragma unroll
        for (int r = 0; r < 4; r++) {
            int m = ty * 4 + r;
            float nm = row_newm[m];
            float sc = row_scale[m];
#pragma unroll
            for (int c = 0; c < 4; c++) {
                float p = __expf(s[r][c] - nm);   // -inf -> 0
                Ps[m * AT_PAD + tx * 4 + c] = p;
                Oacc[r][c] *= (c == 0 && false) ? 1.f : 1.f; // no-op (clarity)
            }
#pragma unroll
            for (int c = 0; c < 4; c++) Oacc[r][c] *= sc;
        }
        __syncthreads();

        // Update l (row sums of P)
        if (tid < 64) {
            float sum = 0.f;
#pragma unroll 8
            for (int n = 0; n < 64; n++) sum += Ps[tid * AT_PAD + n];
            row_l[tid] = row_l[tid] * row_scale[tid] + sum;
        }

        // O += P @ V
#pragma unroll
        for (int kk = 0; kk < 64; kk++) {
            float a[4], bb[4];
#pragma unroll
            for (int r = 0; r < 4; r++) a[r]  = Ps [(ty * 4 + r) * AT_PAD + kk];
#pragma unroll
            for (int c = 0; c < 4; c++) bb[c] = KVs[kk * AT_PAD + tx * 4 + c];
#pragma unroll
            for (int r = 0; r < 4; r++)
#pragma unroll
                for (int c = 0; c < 4; c++)
                    Oacc[r][c] += a[r] * bb[c];
        }
    }
    __syncthreads();

    // Final normalize + write: out[(b*S + q0+m)*D + h*64 + d]
#pragma unroll
    for (int r = 0; r < 4; r++) {
        int m = ty * 4 + r;
        float inv = 1.f / row_l[m];
#pragma unroll
        for (int c = 0; c < 4; c++) {
            int d = tx * 4 + c;
            out[((size_t)(b * SEQ + q0 + m)) * DEMB + h * DHEAD + d] = Oacc[r][c] * inv;
        }
    }
}

// ---------------------------------------------------------------------------
// Launch
// ---------------------------------------------------------------------------
extern "C" void kernel_launch(void* const* d_in, const int* in_sizes, int n_in,
                              void* d_out, int out_size)
{
    (void)in_sizes; (void)n_in; (void)out_size;
    const float* x      = (const float*)d_in[0];
    const float* w_in   = (const float*)d_in[1];
    const float* b_in   = (const float*)d_in[2];
    const float* w_out  = (const float*)d_in[3];
    const float* b_out  = (const float*)d_in[4];
    const int*   causal = (const int*)  d_in[5];
    float* out = (float*)d_out;

    float* qkv = nullptr;
    float* att = nullptr;
    cudaGetSymbolAddress((void**)&qkv, g_qkv);
    cudaGetSymbolAddress((void**)&att, g_att);

    // 1) QKV projection: [8192,1024] @ [3072,1024]^T -> [8192,3072]
    {
        dim3 grid(QKV_N / GBN, MROWS / GBM);   // (48, 64)
        gemm_nt_bias<<<grid, 256>>>(x, w_in, b_in, qkv, MROWS, QKV_N, DEMB);
    }

    // 2) Attention
    {
        const int smem = (3 * 64 * AT_PAD + 4 * 64) * sizeof(float);  // ~51 KB
        cudaFuncSetAttribute(attn_kernel, cudaFuncAttributeMaxDynamicSharedMemorySize, smem);
        dim3 grid(SEQ / 64, BATCH * NHEADS);   // (32, 64)
        attn_kernel<<<grid, 256, smem>>>(qkv, att, causal);
    }

    // 3) Output projection: [8192,1024] @ [1024,1024]^T -> [8192,1024]
    {
        dim3 grid(DEMB / GBN, MROWS / GBM);    // (16, 64)
        gemm_nt_bias<<<grid, 256>>>(att, w_out, b_out, out, MROWS, DEMB, DEMB);
    }
}

// round 3
// speedup vs baseline: 1.6411x; 1.6411x over previous
#include <cuda_runtime.h>
#include <cuda_bf16.h>
#include <math.h>
#include <stdint.h>

// ---------------------------------------------------------------------------
// Problem constants
// ---------------------------------------------------------------------------
#define BATCH   4
#define SEQ     2048
#define DEMB    1024
#define NHEADS  16
#define DHEAD   64
#define MROWS   (BATCH * SEQ)        // 8192
#define QKV_N   (3 * DEMB)           // 3072

// Scratch (device globals: allocation-free per harness rules)
__device__ float g_qkv[(size_t)MROWS * QKV_N];   // 96 MB
__device__ float g_att[(size_t)MROWS * DEMB];    // 32 MB

// bf16 hi/lo split buffers
__device__ __nv_bfloat16 g_xhi[(size_t)MROWS * DEMB];
__device__ __nv_bfloat16 g_xlo[(size_t)MROWS * DEMB];
__device__ __nv_bfloat16 g_wihi[(size_t)QKV_N * DEMB];
__device__ __nv_bfloat16 g_wilo[(size_t)QKV_N * DEMB];
__device__ __nv_bfloat16 g_ahi[(size_t)MROWS * DEMB];
__device__ __nv_bfloat16 g_alo[(size_t)MROWS * DEMB];
__device__ __nv_bfloat16 g_wohi[(size_t)DEMB * DEMB];
__device__ __nv_bfloat16 g_wolo[(size_t)DEMB * DEMB];

// ---------------------------------------------------------------------------
// PTX helpers (base sm_103-safe: mma.sync / ldmatrix / cp.async only)
// ---------------------------------------------------------------------------
__device__ __forceinline__ uint32_t smem_u32(const void* p) {
    uint32_t a;
    asm("{ .reg .u64 t; cvta.to.shared.u64 t, %1; cvt.u32.u64 %0, t; }" : "=r"(a) : "l"(p));
    return a;
}

__device__ __forceinline__ void cp_async16(uint32_t saddr, const void* gaddr) {
    asm volatile("cp.async.ca.shared.global [%0], [%1], 16;" :: "r"(saddr), "l"(gaddr));
}
__device__ __forceinline__ void cp_commit() {
    asm volatile("cp.async.commit_group;");
}
template <int N>
__device__ __forceinline__ void cp_wait() {
    asm volatile("cp.async.wait_group %0;" :: "n"(N));
}

__device__ __forceinline__ void ldsm_x4(uint32_t addr, uint32_t& r0, uint32_t& r1,
                                        uint32_t& r2, uint32_t& r3) {
    asm volatile("ldmatrix.sync.aligned.m8n8.x4.shared.b16 {%0,%1,%2,%3}, [%4];"
                 : "=r"(r0), "=r"(r1), "=r"(r2), "=r"(r3) : "r"(addr));
}

__device__ __forceinline__ void mma_bf16(float* c, const uint32_t* a, uint32_t b0, uint32_t b1) {
    asm volatile(
        "mma.sync.aligned.m16n8k16.row.col.f32.bf16.bf16.f32 "
        "{%0,%1,%2,%3}, {%4,%5,%6,%7}, {%8,%9}, {%0,%1,%2,%3};"
        : "+f"(c[0]), "+f"(c[1]), "+f"(c[2]), "+f"(c[3])
        : "r"(a[0]), "r"(a[1]), "r"(a[2]), "r"(a[3]), "r"(b0), "r"(b1));
}

// ---------------------------------------------------------------------------
// fp32 -> bf16 hi/lo split
// ---------------------------------------------------------------------------
__global__ __launch_bounds__(256)
void split_fp32(const float* __restrict__ src, __nv_bfloat16* __restrict__ hi,
                __nv_bfloat16* __restrict__ lo, int n4)
{
    const float4* s4 = (const float4*)src;
    for (int i = blockIdx.x * blockDim.x + threadIdx.x; i < n4; i += gridDim.x * blockDim.x) {
        float4 v = s4[i];
        __nv_bfloat16 h0 = __float2bfloat16(v.x);
        __nv_bfloat16 h1 = __float2bfloat16(v.y);
        __nv_bfloat16 h2 = __float2bfloat16(v.z);
        __nv_bfloat16 h3 = __float2bfloat16(v.w);
        __nv_bfloat16 l0 = __float2bfloat16(v.x - __bfloat162float(h0));
        __nv_bfloat16 l1 = __float2bfloat16(v.y - __bfloat162float(h1));
        __nv_bfloat16 l2 = __float2bfloat16(v.z - __bfloat162float(h2));
        __nv_bfloat16 l3 = __float2bfloat16(v.w - __bfloat162float(h3));
        __nv_bfloat162* hp = (__nv_bfloat162*)(hi + (size_t)i * 4);
        __nv_bfloat162* lp = (__nv_bfloat162*)(lo + (size_t)i * 4);
        hp[0] = __nv_bfloat162(h0, h1); hp[1] = __nv_bfloat162(h2, h3);
        lp[0] = __nv_bfloat162(l0, l1); lp[1] = __nv_bfloat162(l2, l3);
    }
}

// ---------------------------------------------------------------------------
// Tensor-core GEMM via mma.sync:
//   C[M,N] = (Ahi+Alo)[M,K] @ ((Bhi+Blo)[N,K])^T + bias   (3-pass hi/lo)
// CTA tile 128x128, BK=32, 256 threads (8 warps, each 32m x 64n),
// cp.async double-buffered smem, 80B-padded rows (conflict-free ldmatrix).
// ---------------------------------------------------------------------------
#define BM 128
#define BN 128
#define BK 32
#define ROWB 80                       // padded row bytes (32 bf16 = 64B + 16B pad)
#define TILE_SM (128 * ROWB)          // 10240 B per tile
#define STAGE_SM (4 * TILE_SM)        // Ahi,Alo,Bhi,Blo = 40960 B
#define GEMM_SMEM (2 * STAGE_SM)      // 81920 B

__global__ __launch_bounds__(256)
void gemm_mma_bf16x3(const __nv_bfloat16* __restrict__ Ahi, const __nv_bfloat16* __restrict__ Alo,
                     const __nv_bfloat16* __restrict__ Bhi, const __nv_bfloat16* __restrict__ Blo,
                     const float* __restrict__ bias, float* __restrict__ C,
                     int M, int N, int K)
{
    extern __shared__ char smem[];
    const uint32_t sbase = smem_u32(smem);
    const int tid = threadIdx.x;
    const int wid = tid >> 5;
    const int lid = tid & 31;
    const int warpM = wid & 3;            // 4 m-groups of 32 rows
    const int warpN = wid >> 2;           // 2 n-groups of 64 cols
    const int m0 = blockIdx.y * BM;
    const int n0 = blockIdx.x * BN;

    // per-thread load coords: 512 16B segments per tile, 2 per thread
    const int lr0 = tid >> 2;             // row 0..63
    const int lq  = (tid & 3) * 16;       // 16B column offset within 64B row

    const __nv_bfloat16* gsrc[4] = {
        Ahi + (size_t)m0 * K, Alo + (size_t)m0 * K,
        Bhi + (size_t)n0 * K, Blo + (size_t)n0 * K
    };

    float acc[2][8][4];
#pragma unroll
    for (int i = 0; i < 2; i++)
#pragma unroll
        for (int j = 0; j < 8; j++)
#pragma unroll
            for (int k = 0; k < 4; k++) acc[i][j][k] = 0.f;

    const int nch = K / BK;

    // --- async load of one chunk into stage buf ---
    auto load_chunk = [&](int c, int buf) {
        const int k0 = c * BK;
        uint32_t st = sbase + buf * STAGE_SM;
#pragma unroll
        for (int t = 0; t < 4; t++) {
            const __nv_bfloat16* src = gsrc[t] + k0;
#pragma unroll
            for (int i = 0; i < 2; i++) {
                int r = lr0 + i * 64;
                cp_async16(st + t * TILE_SM + r * ROWB + lq,
                           (const char*)(src + (size_t)r * K) + lq);
            }
        }
        cp_commit();
    };

    // --- compute one chunk from stage buf ---
    auto compute_chunk = [&](int buf) {
        uint32_t st   = sbase + buf * STAGE_SM;
        uint32_t sAhi = st;
        uint32_t sAlo = st + TILE_SM;
        uint32_t sBhi = st + 2 * TILE_SM;
        uint32_t sBlo = st + 3 * TILE_SM;

#pragma unroll
        for (int ks = 0; ks < 2; ks++) {
            // A fragments (hi, lo) for both 16-row m-tiles
            uint32_t ahi[2][4], alo[2][4];
            {
                int arow = warpM * 32 + (lid & 15);
                int acol = ks * 32 + (lid >> 4) * 16;
#pragma unroll
                for (int mt = 0; mt < 2; mt++) {
                    uint32_t off = (arow + mt * 16) * ROWB + acol;
                    ldsm_x4(sAhi + off, ahi[mt][0], ahi[mt][1], ahi[mt][2], ahi[mt][3]);
                    ldsm_x4(sAlo + off, alo[mt][0], alo[mt][1], alo[mt][2], alo[mt][3]);
                }
            }
            // B fragments: 4 pairs of n8-tiles
            int brow_l = (lid >> 4) * 8 + (lid & 7);
            int bcol   = ks * 32 + ((lid >> 3) & 1) * 16;
#pragma unroll
            for (int nt = 0; nt < 4; nt++) {
                uint32_t off = (warpN * 64 + nt * 16 + brow_l) * ROWB + bcol;
                uint32_t bh[4], bl[4];
                ldsm_x4(sBhi + off, bh[0], bh[1], bh[2], bh[3]);
                ldsm_x4(sBlo + off, bl[0], bl[1], bl[2], bl[3]);
#pragma unroll
                for (int mt = 0; mt < 2; mt++) {
#pragma unroll
                    for (int h = 0; h < 2; h++) {
                        float* c = acc[mt][nt * 2 + h];
                        mma_bf16(c, ahi[mt], bh[2 * h], bh[2 * h + 1]);  // hi*hi
                        mma_bf16(c, ahi[mt], bl[2 * h], bl[2 * h + 1]);  // hi*lo
                        mma_bf16(c, alo[mt], bh[2 * h], bh[2 * h + 1]);  // lo*hi
                    }
                }
            }
        }
    };

    // --- pipelined main loop ---
    load_chunk(0, 0);
    for (int c = 0; c < nch; c++) {
        if (c + 1 < nch) {
            load_chunk(c + 1, (c + 1) & 1);
            cp_wait<1>();
        } else {
            cp_wait<0>();
        }
        __syncthreads();
        compute_chunk(c & 1);
        __syncthreads();
    }

    // --- epilogue: fragment -> global with bias ---
    const int rbase = m0 + warpM * 32 + (lid >> 2);
    const int cbase = n0 + warpN * 64 + 2 * (lid & 3);
#pragma unroll
    for (int mt = 0; mt < 2; mt++) {
#pragma unroll
        for (int nt = 0; nt < 8; nt++) {
            int col = cbase + nt * 8;
            float b0 = __ldg(bias + col);
            float b1 = __ldg(bias + col + 1);
            int r0 = rbase + mt * 16;
            float2 v0 = make_float2(acc[mt][nt][0] + b0, acc[mt][nt][1] + b1);
            float2 v1 = make_float2(acc[mt][nt][2] + b0, acc[mt][nt][3] + b1);
            *(float2*)&C[(size_t)r0 * N + col]       = v0;
            *(float2*)&C[(size_t)(r0 + 8) * N + col] = v1;
        }
    }
}

// ---------------------------------------------------------------------------
// Flash attention (fp32, online softmax, causal) — unchanged
// ---------------------------------------------------------------------------
#define AT_PAD 65

__global__ __launch_bounds__(256)
void attn_kernel(const float* __restrict__ qkv, float* __restrict__ out,
                 const int* __restrict__ causal_flag)
{
    extern __shared__ float sm[];
    float* Qs        = sm;
    float* KVs       = Qs  + 64 * AT_PAD;
    float* Ps        = KVs + 64 * AT_PAD;
    float* row_m     = Ps  + 64 * AT_PAD;
    float* row_l     = row_m + 64;
    float* row_scale = row_l + 64;
    float* row_newm  = row_scale + 64;

    const int tid = threadIdx.x;
    const int tx  = tid & 15;
    const int ty  = tid >> 4;
    const int iq  = blockIdx.x;
    const int bh  = blockIdx.y;
    const int b   = bh >> 4;
    const int h   = bh & 15;
    const int q0  = iq * 64;
    const int causal = *causal_flag;

    const float* base = qkv + (size_t)b * SEQ * QKV_N + h * DHEAD;

    for (int idx = tid; idx < 64 * 64; idx += 256) {
        int m = idx >> 6, d = idx & 63;
        Qs[d * AT_PAD + m] = base[(size_t)(q0 + m) * QKV_N + d];
    }
    if (tid < 64) { row_m[tid] = -INFINITY; row_l[tid] = 0.f; }

    float Oacc[4][4];
#pragma unroll
    for (int r = 0; r < 4; r++)
#pragma unroll
        for (int c = 0; c < 4; c++) Oacc[r][c] = 0.f;

    const int ntiles = causal ? (iq + 1) : (SEQ / 64);
    const float scale = 0.125f;

    for (int jk = 0; jk < ntiles; jk++) {
        const int k0 = jk * 64;
        __syncthreads();

        for (int idx = tid; idx < 64 * 64; idx += 256) {
            int n = idx >> 6, d = idx & 63;
            KVs[d * AT_PAD + n] = base[(size_t)(k0 + n) * QKV_N + DEMB + d];
        }
        __syncthreads();

        float s[4][4];
#pragma unroll
        for (int r = 0; r < 4; r++)
#pragma unroll
            for (int c = 0; c < 4; c++) s[r][c] = 0.f;
#pragma unroll
        for (int d = 0; d < 64; d++) {
            float a[4], bb[4];
#pragma unroll
            for (int r = 0; r < 4; r++) a[r]  = Qs [d * AT_PAD + ty * 4 + r];
#pragma unroll
            for (int c = 0; c < 4; c++) bb[c] = KVs[d * AT_PAD + tx * 4 + c];
#pragma unroll
            for (int r = 0; r < 4; r++)
#pragma unroll
                for (int c = 0; c < 4; c++)
                    s[r][c] += a[r] * bb[c];
        }

        const bool diag = causal && (jk == iq);
#pragma unroll
        for (int r = 0; r < 4; r++) {
            int m = ty * 4 + r;
#pragma unroll
            for (int c = 0; c < 4; c++) {
                int n = tx * 4 + c;
                float v = s[r][c] * scale;
                if (diag && n > m) v = -INFINITY;
                s[r][c] = v;
                Ps[m * AT_PAD + n] = v;
            }
        }
        __syncthreads();

        for (int idx = tid; idx < 64 * 64; idx += 256) {
            int kr = idx >> 6, d = idx & 63;
            KVs[kr * AT_PAD + d] = base[(size_t)(k0 + kr) * QKV_N + 2 * DEMB + d];
        }
        if (tid < 64) {
            float mx = -INFINITY;
#pragma unroll 8
            for (int n = 0; n < 64; n++) mx = fmaxf(mx, Ps[tid * AT_PAD + n]);
            float old = row_m[tid];
            float nm  = fmaxf(old, mx);
            row_newm[tid]  = nm;
            row_scale[tid] = (old == -INFINITY) ? 0.f : __expf(old - nm);
            row_m[tid]     = nm;
        }
        __syncthreads();

#pragma unroll
        for (int r = 0; r < 4; r++) {
            int m = ty * 4 + r;
            float nm = row_newm[m];
            float sc = row_scale[m];
#pragma unroll
            for (int c = 0; c < 4; c++) {
                float p = __expf(s[r][c] - nm);
                Ps[m * AT_PAD + tx * 4 + c] = p;
            }
#pragma unroll
            for (int c = 0; c < 4; c++) Oacc[r][c] *= sc;
        }
        __syncthreads();

        if (tid < 64) {
            float sum = 0.f;
#pragma unroll 8
            for (int n = 0; n < 64; n++) sum += Ps[tid * AT_PAD + n];
            row_l[tid] = row_l[tid] * row_scale[tid] + sum;
        }

#pragma unroll
        for (int kk = 0; kk < 64; kk++) {
            float a[4], bb[4];
#pragma unroll
            for (int r = 0; r < 4; r++) a[r]  = Ps [(ty * 4 + r) * AT_PAD + kk];
#pragma unroll
            for (int c = 0; c < 4; c++) bb[c] = KVs[kk * AT_PAD + tx * 4 + c];
#pragma unroll
            for (int r = 0; r < 4; r++)
#pragma unroll
                for (int c = 0; c < 4; c++)
                    Oacc[r][c] += a[r] * bb[c];
        }
    }
    __syncthreads();

#pragma unroll
    for (int r = 0; r < 4; r++) {
        int m = ty * 4 + r;
        float inv = 1.f / row_l[m];
#pragma unroll
        for (int c = 0; c < 4; c++) {
            int d = tx * 4 + c;
            out[((size_t)(b * SEQ + q0 + m)) * DEMB + h * DHEAD + d] = Oacc[r][c] * inv;
        }
    }
}

// ---------------------------------------------------------------------------
// Launch
// ---------------------------------------------------------------------------
extern "C" void kernel_launch(void* const* d_in, const int* in_sizes, int n_in,
                              void* d_out, int out_size)
{
    (void)in_sizes; (void)n_in; (void)out_size;
    const float* x      = (const float*)d_in[0];
    const float* w_in   = (const float*)d_in[1];
    const float* b_in   = (const float*)d_in[2];
    const float* w_out  = (const float*)d_in[3];
    const float* b_out  = (const float*)d_in[4];
    const int*   causal = (const int*)  d_in[5];
    float* out = (float*)d_out;

    float* qkv = nullptr;  float* att = nullptr;
    __nv_bfloat16 *xhi, *xlo, *wihi, *wilo, *ahi, *alo, *wohi, *wolo;
    cudaGetSymbolAddress((void**)&qkv, g_qkv);
    cudaGetSymbolAddress((void**)&att, g_att);
    cudaGetSymbolAddress((void**)&xhi, g_xhi);
    cudaGetSymbolAddress((void**)&xlo, g_xlo);
    cudaGetSymbolAddress((void**)&wihi, g_wihi);
    cudaGetSymbolAddress((void**)&wilo, g_wilo);
    cudaGetSymbolAddress((void**)&ahi, g_ahi);
    cudaGetSymbolAddress((void**)&alo, g_alo);
    cudaGetSymbolAddress((void**)&wohi, g_wohi);
    cudaGetSymbolAddress((void**)&wolo, g_wolo);

    cudaFuncSetAttribute(gemm_mma_bf16x3, cudaFuncAttributeMaxDynamicSharedMemorySize, GEMM_SMEM);

    // 1) split x and w_in to bf16 hi/lo
    split_fp32<<<1024, 256>>>(x, xhi, xlo, (MROWS * DEMB) / 4);
    split_fp32<<<512, 256>>>(w_in, wihi, wilo, (QKV_N * DEMB) / 4);

    // 2) QKV projection on tensor cores: [8192,1024] @ [3072,1024]^T
    {
        dim3 grid(QKV_N / BN, MROWS / BM);     // (24, 64)
        gemm_mma_bf16x3<<<grid, 256, GEMM_SMEM>>>(xhi, xlo, wihi, wilo, b_in, qkv,
                                                  MROWS, QKV_N, DEMB);
    }

    // 3) Attention (fp32 SIMT)
    {
        const int smem = (3 * 64 * AT_PAD + 4 * 64) * sizeof(float);
        cudaFuncSetAttribute(attn_kernel, cudaFuncAttributeMaxDynamicSharedMemorySize, smem);
        dim3 grid(SEQ / 64, BATCH * NHEADS);
        attn_kernel<<<grid, 256, smem>>>(qkv, att, causal);
    }

    // 4) split attention output and w_out
    split_fp32<<<1024, 256>>>(att, ahi, alo, (MROWS * DEMB) / 4);
    split_fp32<<<256, 256>>>(w_out, wohi, wolo, (DEMB * DEMB) / 4);

    // 5) Output projection on tensor cores: [8192,1024] @ [1024,1024]^T
    {
        dim3 grid(DEMB / BN, MROWS / BM);      // (8, 64)
        gemm_mma_bf16x3<<<grid, 256, GEMM_SMEM>>>(ahi, alo, wohi, wolo, b_out, out,
                                                  MROWS, DEMB, DEMB);
    }
}

// round 4
// speedup vs baseline: 3.0587x; 1.8638x over previous
#include <cuda_runtime.h>
#include <cuda_bf16.h>
#include <math.h>
#include <stdint.h>

// ---------------------------------------------------------------------------
// Problem constants
// ---------------------------------------------------------------------------
#define BATCH   4
#define SEQ     2048
#define DEMB    1024
#define NHEADS  16
#define DHEAD   64
#define MROWS   (BATCH * SEQ)        // 8192
#define QKV_N   (3 * DEMB)           // 3072

// Scratch (device globals)
__device__ float g_qkv[(size_t)MROWS * QKV_N];   // 96 MB
__device__ float g_att[(size_t)MROWS * DEMB];    // 32 MB

// bf16 hi/lo split buffers for GEMMs
__device__ __nv_bfloat16 g_xhi[(size_t)MROWS * DEMB];
__device__ __nv_bfloat16 g_xlo[(size_t)MROWS * DEMB];
__device__ __nv_bfloat16 g_wihi[(size_t)QKV_N * DEMB];
__device__ __nv_bfloat16 g_wilo[(size_t)QKV_N * DEMB];
__device__ __nv_bfloat16 g_ahi[(size_t)MROWS * DEMB];
__device__ __nv_bfloat16 g_alo[(size_t)MROWS * DEMB];
__device__ __nv_bfloat16 g_wohi[(size_t)DEMB * DEMB];
__device__ __nv_bfloat16 g_wolo[(size_t)DEMB * DEMB];

// head-major bf16 hi/lo for attention: [b][h][s][64]
__device__ __nv_bfloat16 g_qh[(size_t)MROWS * DEMB];
__device__ __nv_bfloat16 g_ql[(size_t)MROWS * DEMB];
__device__ __nv_bfloat16 g_kh[(size_t)MROWS * DEMB];
__device__ __nv_bfloat16 g_kl[(size_t)MROWS * DEMB];
__device__ __nv_bfloat16 g_vh[(size_t)MROWS * DEMB];
__device__ __nv_bfloat16 g_vl[(size_t)MROWS * DEMB];

// ---------------------------------------------------------------------------
// PTX helpers (base sm_103-safe)
// ---------------------------------------------------------------------------
__device__ __forceinline__ uint32_t smem_u32(const void* p) {
    uint32_t a;
    asm("{ .reg .u64 t; cvta.to.shared.u64 t, %1; cvt.u32.u64 %0, t; }" : "=r"(a) : "l"(p));
    return a;
}
__device__ __forceinline__ void cp_async16(uint32_t saddr, const void* gaddr) {
    asm volatile("cp.async.ca.shared.global [%0], [%1], 16;" :: "r"(saddr), "l"(gaddr));
}
__device__ __forceinline__ void cp_commit() { asm volatile("cp.async.commit_group;"); }
template <int N>
__device__ __forceinline__ void cp_wait() { asm volatile("cp.async.wait_group %0;" :: "n"(N)); }

__device__ __forceinline__ void ldsm_x4(uint32_t addr, uint32_t& r0, uint32_t& r1,
                                        uint32_t& r2, uint32_t& r3) {
    asm volatile("ldmatrix.sync.aligned.m8n8.x4.shared.b16 {%0,%1,%2,%3}, [%4];"
                 : "=r"(r0), "=r"(r1), "=r"(r2), "=r"(r3) : "r"(addr));
}
__device__ __forceinline__ void ldsm_x4_t(uint32_t addr, uint32_t& r0, uint32_t& r1,
                                          uint32_t& r2, uint32_t& r3) {
    asm volatile("ldmatrix.sync.aligned.m8n8.x4.trans.shared.b16 {%0,%1,%2,%3}, [%4];"
                 : "=r"(r0), "=r"(r1), "=r"(r2), "=r"(r3) : "r"(addr));
}
__device__ __forceinline__ void mma_bf16(float* c, const uint32_t* a, uint32_t b0, uint32_t b1) {
    asm volatile(
        "mma.sync.aligned.m16n8k16.row.col.f32.bf16.bf16.f32 "
        "{%0,%1,%2,%3}, {%4,%5,%6,%7}, {%8,%9}, {%0,%1,%2,%3};"
        : "+f"(c[0]), "+f"(c[1]), "+f"(c[2]), "+f"(c[3])
        : "r"(a[0]), "r"(a[1]), "r"(a[2]), "r"(a[3]), "r"(b0), "r"(b1));
}

__device__ __forceinline__ uint32_t pack2(float x, float y) {
    __nv_bfloat162 t = __floats2bfloat162_rn(x, y);
    return *(uint32_t*)&t;
}
__device__ __forceinline__ void split2(float x, float y, uint32_t& hi, uint32_t& lo) {
    __nv_bfloat16 hx = __float2bfloat16(x);
    __nv_bfloat16 hy = __float2bfloat16(y);
    __nv_bfloat162 h2(hx, hy);
    hi = *(uint32_t*)&h2;
    lo = pack2(x - __bfloat162float(hx), y - __bfloat162float(hy));
}

// ---------------------------------------------------------------------------
// fp32 -> bf16 hi/lo split (generic, for GEMM operands)
// ---------------------------------------------------------------------------
__global__ __launch_bounds__(256)
void split_fp32(const float* __restrict__ src, __nv_bfloat16* __restrict__ hi,
                __nv_bfloat16* __restrict__ lo, int n4)
{
    const float4* s4 = (const float4*)src;
    for (int i = blockIdx.x * blockDim.x + threadIdx.x; i < n4; i += gridDim.x * blockDim.x) {
        float4 v = s4[i];
        __nv_bfloat16 h0 = __float2bfloat16(v.x);
        __nv_bfloat16 h1 = __float2bfloat16(v.y);
        __nv_bfloat16 h2 = __float2bfloat16(v.z);
        __nv_bfloat16 h3 = __float2bfloat16(v.w);
        __nv_bfloat16 l0 = __float2bfloat16(v.x - __bfloat162float(h0));
        __nv_bfloat16 l1 = __float2bfloat16(v.y - __bfloat162float(h1));
        __nv_bfloat16 l2 = __float2bfloat16(v.z - __bfloat162float(h2));
        __nv_bfloat16 l3 = __float2bfloat16(v.w - __bfloat162float(h3));
        __nv_bfloat162* hp = (__nv_bfloat162*)(hi + (size_t)i * 4);
        __nv_bfloat162* lp = (__nv_bfloat162*)(lo + (size_t)i * 4);
        hp[0] = __nv_bfloat162(h0, h1); hp[1] = __nv_bfloat162(h2, h3);
        lp[0] = __nv_bfloat162(l0, l1); lp[1] = __nv_bfloat162(l2, l3);
    }
}

// ---------------------------------------------------------------------------
// qkv fp32 [b][s][3D] -> head-major bf16 hi/lo [b][h][s][64]; q scaled by 1/8
// ---------------------------------------------------------------------------
struct bf16x4 { __nv_bfloat162 a, b; };

__device__ __forceinline__ void store_split4(__nv_bfloat16* hi, __nv_bfloat16* lo,
                                             size_t idx, float4 v, float s)
{
    float x0 = v.x * s, x1 = v.y * s, x2 = v.z * s, x3 = v.w * s;
    __nv_bfloat16 h0 = __float2bfloat16(x0), h1 = __float2bfloat16(x1);
    __nv_bfloat16 h2 = __float2bfloat16(x2), h3 = __float2bfloat16(x3);
    bf16x4 hv = { __nv_bfloat162(h0, h1), __nv_bfloat162(h2, h3) };
    bf16x4 lv = { __nv_bfloat162(__float2bfloat16(x0 - __bfloat162float(h0)),
                                 __float2bfloat16(x1 - __bfloat162float(h1))),
                  __nv_bfloat162(__float2bfloat16(x2 - __bfloat162float(h2)),
                                 __float2bfloat16(x3 - __bfloat162float(h3))) };
    *(bf16x4*)(hi + idx) = hv;
    *(bf16x4*)(lo + idx) = lv;
}

__global__ __launch_bounds__(256)
void split_qkv(const float* __restrict__ qkv,
               __nv_bfloat16* __restrict__ qh, __nv_bfloat16* __restrict__ ql,
               __nv_bfloat16* __restrict__ kh, __nv_bfloat16* __restrict__ kl,
               __nv_bfloat16* __restrict__ vh, __nv_bfloat16* __restrict__ vl)
{
    const int n4 = MROWS * DEMB / 4;
    for (int i = blockIdx.x * blockDim.x + threadIdx.x; i < n4; i += gridDim.x * blockDim.x) {
        int e  = i * 4;
        int bs = e >> 10;            // row in [0, 8192)
        int hd = e & 1023;
        int h  = hd >> 6;
        int d  = hd & 63;
        int b  = bs >> 11;           // batch
        int s  = bs & 2047;
        size_t src = (size_t)bs * QKV_N + hd;
        size_t dst = (((size_t)(b * NHEADS + h)) * SEQ + s) * 64 + d;
        float4 q4 = *(const float4*)(qkv + src);
        float4 k4 = *(const float4*)(qkv + src + DEMB);
        float4 v4 = *(const float4*)(qkv + src + 2 * DEMB);
        store_split4(qh, ql, dst, q4, 0.125f);
        store_split4(kh, kl, dst, k4, 1.0f);
        store_split4(vh, vl, dst, v4, 1.0f);
    }
}

// ---------------------------------------------------------------------------
// GEMM via mma.sync (3-pass hi/lo) — unchanged from R3 (passed, ~350 TF/s)
// ---------------------------------------------------------------------------
#define BM 128
#define BN 128
#define BK 32
#define ROWB 80
#define TILE_SM (128 * ROWB)
#define STAGE_SM (4 * TILE_SM)
#define GEMM_SMEM (2 * STAGE_SM)

__global__ __launch_bounds__(256)
void gemm_mma_bf16x3(const __nv_bfloat16* __restrict__ Ahi, const __nv_bfloat16* __restrict__ Alo,
                     const __nv_bfloat16* __restrict__ Bhi, const __nv_bfloat16* __restrict__ Blo,
                     const float* __restrict__ bias, float* __restrict__ C,
                     int M, int N, int K)
{
    extern __shared__ char smem[];
    const uint32_t sbase = smem_u32(smem);
    const int tid = threadIdx.x;
    const int wid = tid >> 5;
    const int lid = tid & 31;
    const int warpM = wid & 3;
    const int warpN = wid >> 2;
    const int m0 = blockIdx.y * BM;
    const int n0 = blockIdx.x * BN;

    const int lr0 = tid >> 2;
    const int lq  = (tid & 3) * 16;

    const __nv_bfloat16* gsrc[4] = {
        Ahi + (size_t)m0 * K, Alo + (size_t)m0 * K,
        Bhi + (size_t)n0 * K, Blo + (size_t)n0 * K
    };

    float acc[2][8][4];
#pragma unroll
    for (int i = 0; i < 2; i++)
#pragma unroll
        for (int j = 0; j < 8; j++)
#pragma unroll
            for (int k = 0; k < 4; k++) acc[i][j][k] = 0.f;

    const int nch = K / BK;

    auto load_chunk = [&](int c, int buf) {
        const int k0 = c * BK;
        uint32_t st = sbase + buf * STAGE_SM;
#pragma unroll
        for (int t = 0; t < 4; t++) {
            const __nv_bfloat16* src = gsrc[t] + k0;
#pragma unroll
            for (int i = 0; i < 2; i++) {
                int r = lr0 + i * 64;
                cp_async16(st + t * TILE_SM + r * ROWB + lq,
                           (const char*)(src + (size_t)r * K) + lq);
            }
        }
        cp_commit();
    };

    auto compute_chunk = [&](int buf) {
        uint32_t st   = sbase + buf * STAGE_SM;
        uint32_t sAhi = st;
        uint32_t sAlo = st + TILE_SM;
        uint32_t sBhi = st + 2 * TILE_SM;
        uint32_t sBlo = st + 3 * TILE_SM;

#pragma unroll
        for (int ks = 0; ks < 2; ks++) {
            uint32_t ahi[2][4], alo[2][4];
            {
                int arow = warpM * 32 + (lid & 15);
                int acol = ks * 32 + (lid >> 4) * 16;
#pragma unroll
                for (int mt = 0; mt < 2; mt++) {
                    uint32_t off = (arow + mt * 16) * ROWB + acol;
                    ldsm_x4(sAhi + off, ahi[mt][0], ahi[mt][1], ahi[mt][2], ahi[mt][3]);
                    ldsm_x4(sAlo + off, alo[mt][0], alo[mt][1], alo[mt][2], alo[mt][3]);
                }
            }
            int brow_l = (lid >> 4) * 8 + (lid & 7);
            int bcol   = ks * 32 + ((lid >> 3) & 1) * 16;
#pragma unroll
            for (int nt = 0; nt < 4; nt++) {
                uint32_t off = (warpN * 64 + nt * 16 + brow_l) * ROWB + bcol;
                uint32_t bh[4], bl[4];
                ldsm_x4(sBhi + off, bh[0], bh[1], bh[2], bh[3]);
                ldsm_x4(sBlo + off, bl[0], bl[1], bl[2], bl[3]);
#pragma unroll
                for (int mt = 0; mt < 2; mt++) {
#pragma unroll
                    for (int h = 0; h < 2; h++) {
                        float* c = acc[mt][nt * 2 + h];
                        mma_bf16(c, ahi[mt], bh[2 * h], bh[2 * h + 1]);
                        mma_bf16(c, ahi[mt], bl[2 * h], bl[2 * h + 1]);
                        mma_bf16(c, alo[mt], bh[2 * h], bh[2 * h + 1]);
                    }
                }
            }
        }
    };

    load_chunk(0, 0);
    for (int c = 0; c < nch; c++) {
        if (c + 1 < nch) { load_chunk(c + 1, (c + 1) & 1); cp_wait<1>(); }
        else             { cp_wait<0>(); }
        __syncthreads();
        compute_chunk(c & 1);
        __syncthreads();
    }

    const int rbase = m0 + warpM * 32 + (lid >> 2);
    const int cbase = n0 + warpN * 64 + 2 * (lid & 3);
#pragma unroll
    for (int mt = 0; mt < 2; mt++) {
#pragma unroll
        for (int nt = 0; nt < 8; nt++) {
            int col = cbase + nt * 8;
            float b0 = __ldg(bias + col);
            float b1 = __ldg(bias + col + 1);
            int r0 = rbase + mt * 16;
            float2 v0 = make_float2(acc[mt][nt][0] + b0, acc[mt][nt][1] + b1);
            float2 v1 = make_float2(acc[mt][nt][2] + b0, acc[mt][nt][3] + b1);
            *(float2*)&C[(size_t)r0 * N + col]       = v0;
            *(float2*)&C[(size_t)(r0 + 8) * N + col] = v1;
        }
    }
}

// ---------------------------------------------------------------------------
// Tensor-core flash attention (mma.sync, 3-pass hi/lo, FA2 fragment softmax)
// Block: 128 threads (4 warps; each warp 16 q-rows). q-tile 64, k-tile 64.
// ---------------------------------------------------------------------------
#define AROWB 144                      // 64 bf16 = 128B + 16B pad
#define ATILE (64 * AROWB)             // 9216
#define AQ_HI 0
#define AQ_LO ATILE
#define ASTG  (2 * ATILE)              // 18432
#define ASTGSZ (4 * ATILE)             // K_hi,K_lo,V_hi,V_lo
#define ATT_SMEM (ASTG + 2 * ASTGSZ)   // 92160

__global__ __launch_bounds__(128)
void attn_mma(const __nv_bfloat16* __restrict__ qh, const __nv_bfloat16* __restrict__ ql,
              const __nv_bfloat16* __restrict__ kh, const __nv_bfloat16* __restrict__ kl,
              const __nv_bfloat16* __restrict__ vh, const __nv_bfloat16* __restrict__ vl,
              float* __restrict__ out, const int* __restrict__ causal_flag)
{
    extern __shared__ char smem[];
    const uint32_t sbase = smem_u32(smem);
    const int tid = threadIdx.x;
    const int wid = tid >> 5;
    const int lid = tid & 31;
    const int iq  = blockIdx.x;
    const int bh  = blockIdx.y;
    const int q0  = iq * 64;
    const int causal = *causal_flag;

    const size_t headbase = (size_t)bh * SEQ * 64;

    // 64x64 bf16 tile loader: gmem (row stride 64) -> smem (row stride 144B)
    auto load_tile = [&](uint32_t sdst, const __nv_bfloat16* g) {
        int row = tid >> 1;
        const char* gr = (const char*)(g + (size_t)row * 64);
        uint32_t sr = sdst + row * AROWB;
#pragma unroll
        for (int i = 0; i < 4; i++) {
            int c = (tid & 1) * 4 + i;
            cp_async16(sr + c * 16, gr + c * 16);
        }
    };

    // ---- Q tile -> fragments ----
    load_tile(sbase + AQ_HI, qh + headbase + (size_t)q0 * 64);
    load_tile(sbase + AQ_LO, ql + headbase + (size_t)q0 * 64);
    cp_commit();
    cp_wait<0>();
    __syncthreads();

    uint32_t qfh[4][4], qfl[4][4];
    {
        int arow = wid * 16 + (lid & 15);
        int acol = (lid >> 4) * 16;
#pragma unroll
        for (int ks = 0; ks < 4; ks++) {
            uint32_t off = arow * AROWB + ks * 32 + acol;
            ldsm_x4(sbase + AQ_HI + off, qfh[ks][0], qfh[ks][1], qfh[ks][2], qfh[ks][3]);
            ldsm_x4(sbase + AQ_LO + off, qfl[ks][0], qfl[ks][1], qfl[ks][2], qfl[ks][3]);
        }
    }

    float Oacc[8][4];
#pragma unroll
    for (int j = 0; j < 8; j++)
#pragma unroll
        for (int c = 0; c < 4; c++) Oacc[j][c] = 0.f;
    float m0 = -INFINITY, m1 = -INFINITY, l0 = 0.f, l1 = 0.f;

    const int ntiles = causal ? (iq + 1) : (SEQ / 64);

    auto load_kv = [&](int jk, int buf) {
        size_t off = headbase + (size_t)jk * 64 * 64;
        uint32_t st = sbase + ASTG + buf * ASTGSZ;
        load_tile(st,             kh + off);
        load_tile(st + ATILE,     kl + off);
        load_tile(st + 2 * ATILE, vh + off);
        load_tile(st + 3 * ATILE, vl + off);
        cp_commit();
    };

    load_kv(0, 0);

    for (int jk = 0; jk < ntiles; jk++) {
        if (jk + 1 < ntiles) { load_kv(jk + 1, (jk + 1) & 1); cp_wait<1>(); }
        else                 { cp_wait<0>(); }
        __syncthreads();

        uint32_t st = sbase + ASTG + (jk & 1) * ASTGSZ;
        uint32_t sKh = st, sKl = st + ATILE, sVh = st + 2 * ATILE, sVl = st + 3 * ATILE;

        // ---- S = Q @ K^T (3-pass) ----
        float S[8][4];
#pragma unroll
        for (int j = 0; j < 8; j++)
#pragma unroll
            for (int c = 0; c < 4; c++) S[j][c] = 0.f;

        {
            int brow = (lid >> 4) * 8 + (lid & 7);
            int bcx  = ((lid >> 3) & 1) * 16;
#pragma unroll
            for (int ks = 0; ks < 4; ks++) {
#pragma unroll
                for (int nt = 0; nt < 4; nt++) {
                    uint32_t off = (nt * 16 + brow) * AROWB + ks * 32 + bcx;
                    uint32_t b_h[4], b_l[4];
                    ldsm_x4(sKh + off, b_h[0], b_h[1], b_h[2], b_h[3]);
                    ldsm_x4(sKl + off, b_l[0], b_l[1], b_l[2], b_l[3]);
#pragma unroll
                    for (int h = 0; h < 2; h++) {
                        float* c = S[nt * 2 + h];
                        mma_bf16(c, qfh[ks], b_h[2 * h], b_h[2 * h + 1]);
                        mma_bf16(c, qfh[ks], b_l[2 * h], b_l[2 * h + 1]);
                        mma_bf16(c, qfl[ks], b_h[2 * h], b_h[2 * h + 1]);
                    }
                }
            }
        }

        // ---- causal mask on diagonal tile ----
        const int k0 = jk * 64;
        if (causal && jk == iq) {
            int rg0 = q0 + wid * 16 + (lid >> 2);
#pragma unroll
            for (int j = 0; j < 8; j++) {
                int cg = k0 + j * 8 + 2 * (lid & 3);
#pragma unroll
                for (int c = 0; c < 4; c++) {
                    int rg = rg0 + (c >> 1) * 8;
                    if (cg + (c & 1) > rg) S[j][c] = -INFINITY;
                }
            }
        }

        // ---- online softmax (rows lid>>2 and +8) ----
        float mx0 = -INFINITY, mx1 = -INFINITY;
#pragma unroll
        for (int j = 0; j < 8; j++) {
            mx0 = fmaxf(mx0, fmaxf(S[j][0], S[j][1]));
            mx1 = fmaxf(mx1, fmaxf(S[j][2], S[j][3]));
        }
        mx0 = fmaxf(mx0, __shfl_xor_sync(0xffffffff, mx0, 1));
        mx0 = fmaxf(mx0, __shfl_xor_sync(0xffffffff, mx0, 2));
        mx1 = fmaxf(mx1, __shfl_xor_sync(0xffffffff, mx1, 1));
        mx1 = fmaxf(mx1, __shfl_xor_sync(0xffffffff, mx1, 2));

        float mn0 = fmaxf(m0, mx0), mn1 = fmaxf(m1, mx1);
        float sc0 = __expf(m0 - mn0), sc1 = __expf(m1 - mn1);

        uint32_t pfh[4][4], pfl[4][4];
        float sum0 = 0.f, sum1 = 0.f;
#pragma unroll
        for (int ks = 0; ks < 4; ks++) {
            // tile 2ks -> a0(a index 0: r0), a1(r1); tile 2ks+1 -> a2, a3
#pragma unroll
            for (int half = 0; half < 2; half++) {
                int j = 2 * ks + half;
                float p0 = __expf(S[j][0] - mn0);
                float p1 = __expf(S[j][1] - mn0);
                float p2 = __expf(S[j][2] - mn1);
                float p3 = __expf(S[j][3] - mn1);
                sum0 += p0 + p1;
                sum1 += p2 + p3;
                split2(p0, p1, pfh[ks][half * 2 + 0], pfl[ks][half * 2 + 0]);
                split2(p2, p3, pfh[ks][half * 2 + 1], pfl[ks][half * 2 + 1]);
            }
        }
        // fix a-register order: need [a0,a1,a2,a3] = [t2ks r0, t2ks r1, t2ks+1 r0, t2ks+1 r1]
        // above loop wrote: half0 -> idx0 (t2ks r0), idx1 (t2ks r1); half1 -> idx2 (t2ks+1 r0), idx3 (t2ks+1 r1)
        // which matches exactly.

        sum0 += __shfl_xor_sync(0xffffffff, sum0, 1);
        sum0 += __shfl_xor_sync(0xffffffff, sum0, 2);
        sum1 += __shfl_xor_sync(0xffffffff, sum1, 1);
        sum1 += __shfl_xor_sync(0xffffffff, sum1, 2);

        l0 = l0 * sc0 + sum0;
        l1 = l1 * sc1 + sum1;
        m0 = mn0; m1 = mn1;

#pragma unroll
        for (int j = 0; j < 8; j++) {
            Oacc[j][0] *= sc0; Oacc[j][1] *= sc0;
            Oacc[j][2] *= sc1; Oacc[j][3] *= sc1;
        }

        // ---- O += P @ V (3-pass, V via ldmatrix.trans) ----
        {
            int vr  = ((lid >> 3) & 1) * 8 + (lid & 7);
            int vcx = (lid >> 4) * 16;
#pragma unroll
            for (int ks = 0; ks < 4; ks++) {
#pragma unroll
                for (int nt = 0; nt < 4; nt++) {
                    uint32_t off = (ks * 16 + vr) * AROWB + nt * 32 + vcx;
                    uint32_t v_h[4], v_l[4];
                    ldsm_x4_t(sVh + off, v_h[0], v_h[1], v_h[2], v_h[3]);
                    ldsm_x4_t(sVl + off, v_l[0], v_l[1], v_l[2], v_l[3]);
#pragma unroll
                    for (int h = 0; h < 2; h++) {
                        float* c = Oacc[nt * 2 + h];
                        mma_bf16(c, pfh[ks], v_h[2 * h], v_h[2 * h + 1]);
                        mma_bf16(c, pfh[ks], v_l[2 * h], v_l[2 * h + 1]);
                        mma_bf16(c, pfl[ks], v_h[2 * h], v_h[2 * h + 1]);
                    }
                }
            }
        }
        __syncthreads();
    }

    // ---- epilogue ----
    const int b = bh >> 4, h = bh & 15;
    const int row0 = q0 + wid * 16 + (lid >> 2);
    float inv0 = 1.f / l0, inv1 = 1.f / l1;
#pragma unroll
    for (int j = 0; j < 8; j++) {
        int col = h * 64 + j * 8 + 2 * (lid & 3);
        *(float2*)&out[(size_t)(b * SEQ + row0) * DEMB + col] =
            make_float2(Oacc[j][0] * inv0, Oacc[j][1] * inv0);
        *(float2*)&out[(size_t)(b * SEQ + row0 + 8) * DEMB + col] =
            make_float2(Oacc[j][2] * inv1, Oacc[j][3] * inv1);
    }
}

// ---------------------------------------------------------------------------
// Launch
// ---------------------------------------------------------------------------
extern "C" void kernel_launch(void* const* d_in, const int* in_sizes, int n_in,
                              void* d_out, int out_size)
{
    (void)in_sizes; (void)n_in; (void)out_size;
    const float* x      = (const float*)d_in[0];
    const float* w_in   = (const float*)d_in[1];
    const float* b_in   = (const float*)d_in[2];
    const float* w_out  = (const float*)d_in[3];
    const float* b_out  = (const float*)d_in[4];
    const int*   causal = (const int*)  d_in[5];
    float* out = (float*)d_out;

    float *qkv, *att;
    __nv_bfloat16 *xhi, *xlo, *wihi, *wilo, *ahi, *alo, *wohi, *wolo;
    __nv_bfloat16 *qh, *ql, *kh, *kl, *vh, *vl;
    cudaGetSymbolAddress((void**)&qkv, g_qkv);
    cudaGetSymbolAddress((void**)&att, g_att);
    cudaGetSymbolAddress((void**)&xhi, g_xhi);
    cudaGetSymbolAddress((void**)&xlo, g_xlo);
    cudaGetSymbolAddress((void**)&wihi, g_wihi);
    cudaGetSymbolAddress((void**)&wilo, g_wilo);
    cudaGetSymbolAddress((void**)&ahi, g_ahi);
    cudaGetSymbolAddress((void**)&alo, g_alo);
    cudaGetSymbolAddress((void**)&wohi, g_wohi);
    cudaGetSymbolAddress((void**)&wolo, g_wolo);
    cudaGetSymbolAddress((void**)&qh, g_qh);
    cudaGetSymbolAddress((void**)&ql, g_ql);
    cudaGetSymbolAddress((void**)&kh, g_kh);
    cudaGetSymbolAddress((void**)&kl, g_kl);
    cudaGetSymbolAddress((void**)&vh, g_vh);
    cudaGetSymbolAddress((void**)&vl, g_vl);

    cudaFuncSetAttribute(gemm_mma_bf16x3, cudaFuncAttributeMaxDynamicSharedMemorySize, GEMM_SMEM);
    cudaFuncSetAttribute(attn_mma, cudaFuncAttributeMaxDynamicSharedMemorySize, ATT_SMEM);

    // 1) split x and w_in
    split_fp32<<<1024, 256>>>(x, xhi, xlo, (MROWS * DEMB) / 4);
    split_fp32<<<512, 256>>>(w_in, wihi, wilo, (QKV_N * DEMB) / 4);

    // 2) QKV projection
    {
        dim3 grid(QKV_N / BN, MROWS / BM);
        gemm_mma_bf16x3<<<grid, 256, GEMM_SMEM>>>(xhi, xlo, wihi, wilo, b_in, qkv,
                                                  MROWS, QKV_N, DEMB);
    }

    // 3) split qkv into head-major bf16 hi/lo (q pre-scaled by 1/8)
    split_qkv<<<1024, 256>>>(qkv, qh, ql, kh, kl, vh, vl);

    // 4) attention on tensor cores
    {
        dim3 grid(SEQ / 64, BATCH * NHEADS);
        attn_mma<<<grid, 128, ATT_SMEM>>>(qh, ql, kh, kl, vh, vl, att, causal);
    }

    // 5) split attention output and w_out
    split_fp32<<<1024, 256>>>(att, ahi, alo, (MROWS * DEMB) / 4);
    split_fp32<<<256, 256>>>(w_out, wohi, wolo, (DEMB * DEMB) / 4);

    // 6) Output projection
    {
        dim3 grid(DEMB / BN, MROWS / BM);
        gemm_mma_bf16x3<<<grid, 256, GEMM_SMEM>>>(ahi, alo, wohi, wolo, b_out, out,
                                                  MROWS, DEMB, DEMB);
    }
}

// round 5
// speedup vs baseline: 3.1868x; 1.0419x over previous
#include <cuda_runtime.h>
#include <cuda_bf16.h>
#include <math.h>
#include <stdint.h>

// ---------------------------------------------------------------------------
// Problem constants
// ---------------------------------------------------------------------------
#define BATCH   4
#define SEQ     2048
#define DEMB    1024
#define NHEADS  16
#define DHEAD   64
#define MROWS   (BATCH * SEQ)        // 8192
#define QKV_N   (3 * DEMB)           // 3072

// bf16 hi/lo scratch (device globals)
__device__ __nv_bfloat16 g_xhi[(size_t)MROWS * DEMB];
__device__ __nv_bfloat16 g_xlo[(size_t)MROWS * DEMB];
__device__ __nv_bfloat16 g_wihi[(size_t)QKV_N * DEMB];
__device__ __nv_bfloat16 g_wilo[(size_t)QKV_N * DEMB];
__device__ __nv_bfloat16 g_wohi[(size_t)DEMB * DEMB];
__device__ __nv_bfloat16 g_wolo[(size_t)DEMB * DEMB];
// head-major attention operands: [b][h][s][64]
__device__ __nv_bfloat16 g_qh[(size_t)MROWS * DEMB];
__device__ __nv_bfloat16 g_ql[(size_t)MROWS * DEMB];
__device__ __nv_bfloat16 g_kh[(size_t)MROWS * DEMB];
__device__ __nv_bfloat16 g_kl[(size_t)MROWS * DEMB];
__device__ __nv_bfloat16 g_vh[(size_t)MROWS * DEMB];
__device__ __nv_bfloat16 g_vl[(size_t)MROWS * DEMB];
// attention output, bf16 hi/lo, (B,S,D) row-major
__device__ __nv_bfloat16 g_ahi[(size_t)MROWS * DEMB];
__device__ __nv_bfloat16 g_alo[(size_t)MROWS * DEMB];

// ---------------------------------------------------------------------------
// PTX helpers (base sm_103-safe)
// ---------------------------------------------------------------------------
__device__ __forceinline__ uint32_t smem_u32(const void* p) {
    uint32_t a;
    asm("{ .reg .u64 t; cvta.to.shared.u64 t, %1; cvt.u32.u64 %0, t; }" : "=r"(a) : "l"(p));
    return a;
}
__device__ __forceinline__ void cp_async16(uint32_t saddr, const void* gaddr) {
    asm volatile("cp.async.ca.shared.global [%0], [%1], 16;" :: "r"(saddr), "l"(gaddr));
}
__device__ __forceinline__ void cp_commit() { asm volatile("cp.async.commit_group;"); }
template <int N>
__device__ __forceinline__ void cp_wait() { asm volatile("cp.async.wait_group %0;" :: "n"(N)); }

__device__ __forceinline__ void ldsm_x4(uint32_t addr, uint32_t& r0, uint32_t& r1,
                                        uint32_t& r2, uint32_t& r3) {
    asm volatile("ldmatrix.sync.aligned.m8n8.x4.shared.b16 {%0,%1,%2,%3}, [%4];"
                 : "=r"(r0), "=r"(r1), "=r"(r2), "=r"(r3) : "r"(addr));
}
__device__ __forceinline__ void ldsm_x4_t(uint32_t addr, uint32_t& r0, uint32_t& r1,
                                          uint32_t& r2, uint32_t& r3) {
    asm volatile("ldmatrix.sync.aligned.m8n8.x4.trans.shared.b16 {%0,%1,%2,%3}, [%4];"
                 : "=r"(r0), "=r"(r1), "=r"(r2), "=r"(r3) : "r"(addr));
}
__device__ __forceinline__ void mma_bf16(float* c, const uint32_t* a, uint32_t b0, uint32_t b1) {
    asm volatile(
        "mma.sync.aligned.m16n8k16.row.col.f32.bf16.bf16.f32 "
        "{%0,%1,%2,%3}, {%4,%5,%6,%7}, {%8,%9}, {%0,%1,%2,%3};"
        : "+f"(c[0]), "+f"(c[1]), "+f"(c[2]), "+f"(c[3])
        : "r"(a[0]), "r"(a[1]), "r"(a[2]), "r"(a[3]), "r"(b0), "r"(b1));
}
__device__ __forceinline__ uint32_t pack2(float x, float y) {
    __nv_bfloat162 t = __floats2bfloat162_rn(x, y);
    return *(uint32_t*)&t;
}
__device__ __forceinline__ void split2(float x, float y, uint32_t& hi, uint32_t& lo) {
    __nv_bfloat16 hx = __float2bfloat16(x);
    __nv_bfloat16 hy = __float2bfloat16(y);
    __nv_bfloat162 h2(hx, hy);
    hi = *(uint32_t*)&h2;
    lo = pack2(x - __bfloat162float(hx), y - __bfloat162float(hy));
}

// ---------------------------------------------------------------------------
// fp32 -> bf16 hi/lo split (for x, w_in, w_out)
// ---------------------------------------------------------------------------
__global__ __launch_bounds__(256)
void split_fp32(const float* __restrict__ src, __nv_bfloat16* __restrict__ hi,
                __nv_bfloat16* __restrict__ lo, int n4)
{
    const float4* s4 = (const float4*)src;
    for (int i = blockIdx.x * blockDim.x + threadIdx.x; i < n4; i += gridDim.x * blockDim.x) {
        float4 v = s4[i];
        __nv_bfloat16 h0 = __float2bfloat16(v.x);
        __nv_bfloat16 h1 = __float2bfloat16(v.y);
        __nv_bfloat16 h2 = __float2bfloat16(v.z);
        __nv_bfloat16 h3 = __float2bfloat16(v.w);
        __nv_bfloat16 l0 = __float2bfloat16(v.x - __bfloat162float(h0));
        __nv_bfloat16 l1 = __float2bfloat16(v.y - __bfloat162float(h1));
        __nv_bfloat16 l2 = __float2bfloat16(v.z - __bfloat162float(h2));
        __nv_bfloat16 l3 = __float2bfloat16(v.w - __bfloat162float(h3));
        __nv_bfloat162* hp = (__nv_bfloat162*)(hi + (size_t)i * 4);
        __nv_bfloat162* lp = (__nv_bfloat162*)(lo + (size_t)i * 4);
        hp[0] = __nv_bfloat162(h0, h1); hp[1] = __nv_bfloat162(h2, h3);
        lp[0] = __nv_bfloat162(l0, l1); lp[1] = __nv_bfloat162(l2, l3);
    }
}

// ---------------------------------------------------------------------------
// GEMM via mma.sync (3-pass hi/lo), single-barrier pipelined mainloop.
// MODE 0: C = acc + bias (fp32 out)
// MODE 1: QKV epilogue — split to bf16 hi/lo head-major [b][h][s][64]
//         (bias added first; q region scaled by 0.125)
// ---------------------------------------------------------------------------
#define BM 128
#define BN 128
#define BK 32
#define ROWB 80
#define TILE_SM (128 * ROWB)
#define STAGE_SM (4 * TILE_SM)
#define GEMM_SMEM (2 * STAGE_SM)

template <int MODE>
__global__ __launch_bounds__(256)
void gemm_mma(const __nv_bfloat16* __restrict__ Ahi, const __nv_bfloat16* __restrict__ Alo,
              const __nv_bfloat16* __restrict__ Bhi, const __nv_bfloat16* __restrict__ Blo,
              const float* __restrict__ bias, float* __restrict__ C,
              __nv_bfloat16* __restrict__ qh, __nv_bfloat16* __restrict__ ql,
              __nv_bfloat16* __restrict__ kh, __nv_bfloat16* __restrict__ kl,
              __nv_bfloat16* __restrict__ vh, __nv_bfloat16* __restrict__ vl,
              int M, int N, int K)
{
    extern __shared__ char smem[];
    const uint32_t sbase = smem_u32(smem);
    const int tid = threadIdx.x;
    const int wid = tid >> 5;
    const int lid = tid & 31;
    const int warpM = wid & 3;
    const int warpN = wid >> 2;
    const int m0 = blockIdx.y * BM;
    const int n0 = blockIdx.x * BN;

    const int lr0 = tid >> 2;
    const int lq  = (tid & 3) * 16;

    const __nv_bfloat16* gsrc[4] = {
        Ahi + (size_t)m0 * K, Alo + (size_t)m0 * K,
        Bhi + (size_t)n0 * K, Blo + (size_t)n0 * K
    };

    float acc[2][8][4];
#pragma unroll
    for (int i = 0; i < 2; i++)
#pragma unroll
        for (int j = 0; j < 8; j++)
#pragma unroll
            for (int k = 0; k < 4; k++) acc[i][j][k] = 0.f;

    const int nch = K / BK;

    auto load_chunk = [&](int c, int buf) {
        const int k0 = c * BK;
        uint32_t st = sbase + buf * STAGE_SM;
#pragma unroll
        for (int t = 0; t < 4; t++) {
            const __nv_bfloat16* src = gsrc[t] + k0;
#pragma unroll
            for (int i = 0; i < 2; i++) {
                int r = lr0 + i * 64;
                cp_async16(st + t * TILE_SM + r * ROWB + lq,
                           (const char*)(src + (size_t)r * K) + lq);
            }
        }
        cp_commit();
    };

    auto compute_chunk = [&](int buf) {
        uint32_t st   = sbase + buf * STAGE_SM;
        uint32_t sAhi = st;
        uint32_t sAlo = st + TILE_SM;
        uint32_t sBhi = st + 2 * TILE_SM;
        uint32_t sBlo = st + 3 * TILE_SM;

#pragma unroll
        for (int ks = 0; ks < 2; ks++) {
            uint32_t ahi[2][4], alo[2][4];
            {
                int arow = warpM * 32 + (lid & 15);
                int acol = ks * 32 + (lid >> 4) * 16;
#pragma unroll
                for (int mt = 0; mt < 2; mt++) {
                    uint32_t off = (arow + mt * 16) * ROWB + acol;
                    ldsm_x4(sAhi + off, ahi[mt][0], ahi[mt][1], ahi[mt][2], ahi[mt][3]);
                    ldsm_x4(sAlo + off, alo[mt][0], alo[mt][1], alo[mt][2], alo[mt][3]);
                }
            }
            int brow_l = (lid >> 4) * 8 + (lid & 7);
            int bcol   = ks * 32 + ((lid >> 3) & 1) * 16;
#pragma unroll
            for (int nt = 0; nt < 4; nt++) {
                uint32_t off = (warpN * 64 + nt * 16 + brow_l) * ROWB + bcol;
                uint32_t bh[4], bl[4];
                ldsm_x4(sBhi + off, bh[0], bh[1], bh[2], bh[3]);
                ldsm_x4(sBlo + off, bl[0], bl[1], bl[2], bl[3]);
#pragma unroll
                for (int mt = 0; mt < 2; mt++) {
#pragma unroll
                    for (int h = 0; h < 2; h++) {
                        float* c = acc[mt][nt * 2 + h];
                        mma_bf16(c, ahi[mt], bh[2 * h], bh[2 * h + 1]);
                        mma_bf16(c, ahi[mt], bl[2 * h], bl[2 * h + 1]);
                        mma_bf16(c, alo[mt], bh[2 * h], bh[2 * h + 1]);
                    }
                }
            }
        }
    };

    // single-barrier pipelined mainloop
    load_chunk(0, 0);
    cp_wait<0>(); __syncthreads();
    for (int c = 0; c < nch; c++) {
        if (c + 1 < nch) load_chunk(c + 1, (c + 1) & 1);
        compute_chunk(c & 1);
        cp_wait<0>(); __syncthreads();
    }

    const int rbase = m0 + warpM * 32 + (lid >> 2);
    const int cbase = n0 + warpN * 64 + 2 * (lid & 3);

    if (MODE == 0) {
#pragma unroll
        for (int mt = 0; mt < 2; mt++) {
#pragma unroll
            for (int nt = 0; nt < 8; nt++) {
                int col = cbase + nt * 8;
                float b0 = __ldg(bias + col);
                float b1 = __ldg(bias + col + 1);
                int r0 = rbase + mt * 16;
                float2 v0 = make_float2(acc[mt][nt][0] + b0, acc[mt][nt][1] + b1);
                float2 v1 = make_float2(acc[mt][nt][2] + b0, acc[mt][nt][3] + b1);
                *(float2*)&C[(size_t)r0 * N + col]       = v0;
                *(float2*)&C[(size_t)(r0 + 8) * N + col] = v1;
            }
        }
    } else {
        // QKV fused epilogue: region t (q/k/v), head-major store of bf16 hi/lo
        const int t = n0 >> 10;
        const float qs = (t == 0) ? 0.125f : 1.0f;
        __nv_bfloat16* dh = (t == 0) ? qh : (t == 1) ? kh : vh;
        __nv_bfloat16* dl = (t == 0) ? ql : (t == 1) ? kl : vl;
#pragma unroll
        for (int mt = 0; mt < 2; mt++) {
#pragma unroll
            for (int nt = 0; nt < 8; nt++) {
                int n  = cbase + nt * 8;
                float b0 = __ldg(bias + n);
                float b1 = __ldg(bias + n + 1);
                int nn = n & 1023;
                int hh = nn >> 6;
                int d  = nn & 63;
                int m  = rbase + mt * 16;
                int bb = m >> 11, ss = m & 2047;
                size_t idx = (((size_t)(bb * NHEADS + hh)) * SEQ + ss) * 64 + d;
                uint32_t hv, lv;
                split2((acc[mt][nt][0] + b0) * qs, (acc[mt][nt][1] + b1) * qs, hv, lv);
                *(uint32_t*)(dh + idx) = hv;
                *(uint32_t*)(dl + idx) = lv;
                int m2 = m + 8;
                bb = m2 >> 11; ss = m2 & 2047;
                idx = (((size_t)(bb * NHEADS + hh)) * SEQ + ss) * 64 + d;
                split2((acc[mt][nt][2] + b0) * qs, (acc[mt][nt][3] + b1) * qs, hv, lv);
                *(uint32_t*)(dh + idx) = hv;
                *(uint32_t*)(dl + idx) = lv;
            }
        }
    }
}

// ---------------------------------------------------------------------------
// Tensor-core flash attention (mma.sync, 3-pass hi/lo, FA2 fragment softmax).
// 128 threads (4 warps x 16 q-rows), q-tile 64, k-tile 64, single-barrier loop.
// Epilogue writes bf16 hi/lo directly (fused split).
// ---------------------------------------------------------------------------
#define AROWB 144
#define ATILE (64 * AROWB)
#define AQ_HI 0
#define AQ_LO ATILE
#define ASTG  (2 * ATILE)
#define ASTGSZ (4 * ATILE)
#define ATT_SMEM (ASTG + 2 * ASTGSZ)   // 92160

__global__ __launch_bounds__(128)
void attn_mma(const __nv_bfloat16* __restrict__ qh, const __nv_bfloat16* __restrict__ ql,
              const __nv_bfloat16* __restrict__ kh, const __nv_bfloat16* __restrict__ kl,
              const __nv_bfloat16* __restrict__ vh, const __nv_bfloat16* __restrict__ vl,
              __nv_bfloat16* __restrict__ ahi, __nv_bfloat16* __restrict__ alo,
              const int* __restrict__ causal_flag)
{
    extern __shared__ char smem[];
    const uint32_t sbase = smem_u32(smem);
    const int tid = threadIdx.x;
    const int wid = tid >> 5;
    const int lid = tid & 31;
    const int iq  = blockIdx.x;
    const int bh  = blockIdx.y;
    const int q0  = iq * 64;
    const int causal = *causal_flag;

    const size_t headbase = (size_t)bh * SEQ * 64;

    auto load_tile = [&](uint32_t sdst, const __nv_bfloat16* g) {
        int row = tid >> 1;
        const char* gr = (const char*)(g + (size_t)row * 64);
        uint32_t sr = sdst + row * AROWB;
#pragma unroll
        for (int i = 0; i < 4; i++) {
            int c = (tid & 1) * 4 + i;
            cp_async16(sr + c * 16, gr + c * 16);
        }
    };

    // Q tiles + first KV stage in flight together
    load_tile(sbase + AQ_HI, qh + headbase + (size_t)q0 * 64);
    load_tile(sbase + AQ_LO, ql + headbase + (size_t)q0 * 64);

    auto load_kv = [&](int jk, int buf) {
        size_t off = headbase + (size_t)jk * 64 * 64;
        uint32_t st = sbase + ASTG + buf * ASTGSZ;
        load_tile(st,             kh + off);
        load_tile(st + ATILE,     kl + off);
        load_tile(st + 2 * ATILE, vh + off);
        load_tile(st + 3 * ATILE, vl + off);
        cp_commit();
    };

    load_kv(0, 0);
    cp_wait<0>(); __syncthreads();

    uint32_t qfh[4][4], qfl[4][4];
    {
        int arow = wid * 16 + (lid & 15);
        int acol = (lid >> 4) * 16;
#pragma unroll
        for (int ks = 0; ks < 4; ks++) {
            uint32_t off = arow * AROWB + ks * 32 + acol;
            ldsm_x4(sbase + AQ_HI + off, qfh[ks][0], qfh[ks][1], qfh[ks][2], qfh[ks][3]);
            ldsm_x4(sbase + AQ_LO + off, qfl[ks][0], qfl[ks][1], qfl[ks][2], qfl[ks][3]);
        }
    }

    float Oacc[8][4];
#pragma unroll
    for (int j = 0; j < 8; j++)
#pragma unroll
        for (int c = 0; c < 4; c++) Oacc[j][c] = 0.f;
    float m0 = -INFINITY, m1 = -INFINITY, l0 = 0.f, l1 = 0.f;

    const int ntiles = causal ? (iq + 1) : (SEQ / 64);

    for (int jk = 0; jk < ntiles; jk++) {
        if (jk + 1 < ntiles) load_kv(jk + 1, (jk + 1) & 1);

        uint32_t st = sbase + ASTG + (jk & 1) * ASTGSZ;
        uint32_t sKh = st, sKl = st + ATILE, sVh = st + 2 * ATILE, sVl = st + 3 * ATILE;

        // ---- S = Q @ K^T (3-pass) ----
        float S[8][4];
#pragma unroll
        for (int j = 0; j < 8; j++)
#pragma unroll
            for (int c = 0; c < 4; c++) S[j][c] = 0.f;
        {
            int brow = (lid >> 4) * 8 + (lid & 7);
            int bcx  = ((lid >> 3) & 1) * 16;
#pragma unroll
            for (int ks = 0; ks < 4; ks++) {
#pragma unroll
                for (int nt = 0; nt < 4; nt++) {
                    uint32_t off = (nt * 16 + brow) * AROWB + ks * 32 + bcx;
                    uint32_t b_h[4], b_l[4];
                    ldsm_x4(sKh + off, b_h[0], b_h[1], b_h[2], b_h[3]);
                    ldsm_x4(sKl + off, b_l[0], b_l[1], b_l[2], b_l[3]);
#pragma unroll
                    for (int h = 0; h < 2; h++) {
                        float* c = S[nt * 2 + h];
                        mma_bf16(c, qfh[ks], b_h[2 * h], b_h[2 * h + 1]);
                        mma_bf16(c, qfh[ks], b_l[2 * h], b_l[2 * h + 1]);
                        mma_bf16(c, qfl[ks], b_h[2 * h], b_h[2 * h + 1]);
                    }
                }
            }
        }

        // ---- causal mask on diagonal tile ----
        const int k0 = jk * 64;
        if (causal && jk == iq) {
            int rg0 = q0 + wid * 16 + (lid >> 2);
#pragma unroll
            for (int j = 0; j < 8; j++) {
                int cg = k0 + j * 8 + 2 * (lid & 3);
#pragma unroll
                for (int c = 0; c < 4; c++) {
                    int rg = rg0 + (c >> 1) * 8;
                    if (cg + (c & 1) > rg) S[j][c] = -INFINITY;
                }
            }
        }

        // ---- online softmax ----
        float mx0 = -INFINITY, mx1 = -INFINITY;
#pragma unroll
        for (int j = 0; j < 8; j++) {
            mx0 = fmaxf(mx0, fmaxf(S[j][0], S[j][1]));
            mx1 = fmaxf(mx1, fmaxf(S[j][2], S[j][3]));
        }
        mx0 = fmaxf(mx0, __shfl_xor_sync(0xffffffff, mx0, 1));
        mx0 = fmaxf(mx0, __shfl_xor_sync(0xffffffff, mx0, 2));
        mx1 = fmaxf(mx1, __shfl_xor_sync(0xffffffff, mx1, 1));
        mx1 = fmaxf(mx1, __shfl_xor_sync(0xffffffff, mx1, 2));

        float mn0 = fmaxf(m0, mx0), mn1 = fmaxf(m1, mx1);
        float sc0 = __expf(m0 - mn0), sc1 = __expf(m1 - mn1);

        uint32_t pfh[4][4], pfl[4][4];
        float sum0 = 0.f, sum1 = 0.f;
#pragma unroll
        for (int ks = 0; ks < 4; ks++) {
#pragma unroll
            for (int half = 0; half < 2; half++) {
                int j = 2 * ks + half;
                float p0 = __expf(S[j][0] - mn0);
                float p1 = __expf(S[j][1] - mn0);
                float p2 = __expf(S[j][2] - mn1);
                float p3 = __expf(S[j][3] - mn1);
                sum0 += p0 + p1;
                sum1 += p2 + p3;
                split2(p0, p1, pfh[ks][half * 2 + 0], pfl[ks][half * 2 + 0]);
                split2(p2, p3, pfh[ks][half * 2 + 1], pfl[ks][half * 2 + 1]);
            }
        }
        sum0 += __shfl_xor_sync(0xffffffff, sum0, 1);
        sum0 += __shfl_xor_sync(0xffffffff, sum0, 2);
        sum1 += __shfl_xor_sync(0xffffffff, sum1, 1);
        sum1 += __shfl_xor_sync(0xffffffff, sum1, 2);

        l0 = l0 * sc0 + sum0;
        l1 = l1 * sc1 + sum1;
        m0 = mn0; m1 = mn1;

#pragma unroll
        for (int j = 0; j < 8; j++) {
            Oacc[j][0] *= sc0; Oacc[j][1] *= sc0;
            Oacc[j][2] *= sc1; Oacc[j][3] *= sc1;
        }

        // ---- O += P @ V (3-pass, V via ldmatrix.trans) ----
        {
            int vr  = ((lid >> 3) & 1) * 8 + (lid & 7);
            int vcx = (lid >> 4) * 16;
#pragma unroll
            for (int ks = 0; ks < 4; ks++) {
#pragma unroll
                for (int nt = 0; nt < 4; nt++) {
                    uint32_t off = (ks * 16 + vr) * AROWB + nt * 32 + vcx;
                    uint32_t v_h[4], v_l[4];
                    ldsm_x4_t(sVh + off, v_h[0], v_h[1], v_h[2], v_h[3]);
                    ldsm_x4_t(sVl + off, v_l[0], v_l[1], v_l[2], v_l[3]);
#pragma unroll
                    for (int h = 0; h < 2; h++) {
                        float* c = Oacc[nt * 2 + h];
                        mma_bf16(c, pfh[ks], v_h[2 * h], v_h[2 * h + 1]);
                        mma_bf16(c, pfh[ks], v_l[2 * h], v_l[2 * h + 1]);
                        mma_bf16(c, pfl[ks], v_h[2 * h], v_h[2 * h + 1]);
                    }
                }
            }
        }
        cp_wait<0>(); __syncthreads();
    }

    // ---- epilogue: fused fp32->bf16 hi/lo split, (B,S,D) row-major ----
    const int b = bh >> 4, h = bh & 15;
    const int row0 = q0 + wid * 16 + (lid >> 2);
    float inv0 = 1.f / l0, inv1 = 1.f / l1;
#pragma unroll
    for (int j = 0; j < 8; j++) {
        int col = h * 64 + j * 8 + 2 * (lid & 3);
        size_t idx0 = (size_t)(b * SEQ + row0) * DEMB + col;
        size_t idx1 = (size_t)(b * SEQ + row0 + 8) * DEMB + col;
        uint32_t hv, lv;
        split2(Oacc[j][0] * inv0, Oacc[j][1] * inv0, hv, lv);
        *(uint32_t*)(ahi + idx0) = hv;
        *(uint32_t*)(alo + idx0) = lv;
        split2(Oacc[j][2] * inv1, Oacc[j][3] * inv1, hv, lv);
        *(uint32_t*)(ahi + idx1) = hv;
        *(uint32_t*)(alo + idx1) = lv;
    }
}

// ---------------------------------------------------------------------------
// Launch
// ---------------------------------------------------------------------------
extern "C" void kernel_launch(void* const* d_in, const int* in_sizes, int n_in,
                              void* d_out, int out_size)
{
    (void)in_sizes; (void)n_in; (void)out_size;
    const float* x      = (const float*)d_in[0];
    const float* w_in   = (const float*)d_in[1];
    const float* b_in   = (const float*)d_in[2];
    const float* w_out  = (const float*)d_in[3];
    const float* b_out  = (const float*)d_in[4];
    const int*   causal = (const int*)  d_in[5];
    float* out = (float*)d_out;

    __nv_bfloat16 *xhi, *xlo, *wihi, *wilo, *wohi, *wolo;
    __nv_bfloat16 *qh, *ql, *kh, *kl, *vh, *vl, *ahi, *alo;
    cudaGetSymbolAddress((void**)&xhi, g_xhi);
    cudaGetSymbolAddress((void**)&xlo, g_xlo);
    cudaGetSymbolAddress((void**)&wihi, g_wihi);
    cudaGetSymbolAddress((void**)&wilo, g_wilo);
    cudaGetSymbolAddress((void**)&wohi, g_wohi);
    cudaGetSymbolAddress((void**)&wolo, g_wolo);
    cudaGetSymbolAddress((void**)&qh, g_qh);
    cudaGetSymbolAddress((void**)&ql, g_ql);
    cudaGetSymbolAddress((void**)&kh, g_kh);
    cudaGetSymbolAddress((void**)&kl, g_kl);
    cudaGetSymbolAddress((void**)&vh, g_vh);
    cudaGetSymbolAddress((void**)&vl, g_vl);
    cudaGetSymbolAddress((void**)&ahi, g_ahi);
    cudaGetSymbolAddress((void**)&alo, g_alo);

    cudaFuncSetAttribute(gemm_mma<0>, cudaFuncAttributeMaxDynamicSharedMemorySize, GEMM_SMEM);
    cudaFuncSetAttribute(gemm_mma<1>, cudaFuncAttributeMaxDynamicSharedMemorySize, GEMM_SMEM);
    cudaFuncSetAttribute(attn_mma, cudaFuncAttributeMaxDynamicSharedMemorySize, ATT_SMEM);

    // 1) split inputs
    split_fp32<<<1024, 256>>>(x, xhi, xlo, (MROWS * DEMB) / 4);
    split_fp32<<<512, 256>>>(w_in, wihi, wilo, (QKV_N * DEMB) / 4);
    split_fp32<<<256, 256>>>(w_out, wohi, wolo, (DEMB * DEMB) / 4);

    // 2) QKV projection, fused head-major hi/lo split epilogue
    {
        dim3 grid(QKV_N / BN, MROWS / BM);
        gemm_mma<1><<<grid, 256, GEMM_SMEM>>>(xhi, xlo, wihi, wilo, b_in, nullptr,
                                              qh, ql, kh, kl, vh, vl,
                                              MROWS, QKV_N, DEMB);
    }

    // 3) attention, fused hi/lo split epilogue
    {
        dim3 grid(SEQ / 64, BATCH * NHEADS);
        attn_mma<<<grid, 128, ATT_SMEM>>>(qh, ql, kh, kl, vh, vl, ahi, alo, causal);
    }

    // 4) output projection (fp32 + bias)
    {
        dim3 grid(DEMB / BN, MROWS / BM);
        gemm_mma<0><<<grid, 256, GEMM_SMEM>>>(ahi, alo, wohi, wolo, b_out, out,
                                              nullptr, nullptr, nullptr, nullptr, nullptr, nullptr,
                                              MROWS, DEMB, DEMB);
    }
}

// round 6
// speedup vs baseline: 3.3993x; 1.0667x over previous
#include <cuda_runtime.h>
#include <cuda_bf16.h>
#include <math.h>
#include <stdint.h>

// ---------------------------------------------------------------------------
// Problem constants
// ---------------------------------------------------------------------------
#define BATCH   4
#define SEQ     2048
#define DEMB    1024
#define NHEADS  16
#define DHEAD   64
#define MROWS   (BATCH * SEQ)        // 8192
#define QKV_N   (3 * DEMB)           // 3072

// bf16 hi/lo scratch (device globals)
__device__ __nv_bfloat16 g_xhi[(size_t)MROWS * DEMB];
__device__ __nv_bfloat16 g_xlo[(size_t)MROWS * DEMB];
__device__ __nv_bfloat16 g_wihi[(size_t)QKV_N * DEMB];
__device__ __nv_bfloat16 g_wilo[(size_t)QKV_N * DEMB];
__device__ __nv_bfloat16 g_wohi[(size_t)DEMB * DEMB];
__device__ __nv_bfloat16 g_wolo[(size_t)DEMB * DEMB];
// head-major attention operands: [b][h][s][64]
__device__ __nv_bfloat16 g_qh[(size_t)MROWS * DEMB];
__device__ __nv_bfloat16 g_ql[(size_t)MROWS * DEMB];
__device__ __nv_bfloat16 g_kh[(size_t)MROWS * DEMB];
__device__ __nv_bfloat16 g_kl[(size_t)MROWS * DEMB];
__device__ __nv_bfloat16 g_vh[(size_t)MROWS * DEMB];
__device__ __nv_bfloat16 g_vl[(size_t)MROWS * DEMB];
// attention output, bf16 hi/lo, (B,S,D) row-major
__device__ __nv_bfloat16 g_ahi[(size_t)MROWS * DEMB];
__device__ __nv_bfloat16 g_alo[(size_t)MROWS * DEMB];

// ---------------------------------------------------------------------------
// PTX helpers (base sm_103-safe)
// ---------------------------------------------------------------------------
__device__ __forceinline__ uint32_t smem_u32(const void* p) {
    uint32_t a;
    asm("{ .reg .u64 t; cvta.to.shared.u64 t, %1; cvt.u32.u64 %0, t; }" : "=r"(a) : "l"(p));
    return a;
}
__device__ __forceinline__ void cp_async16(uint32_t saddr, const void* gaddr) {
    asm volatile("cp.async.ca.shared.global [%0], [%1], 16;" :: "r"(saddr), "l"(gaddr));
}
__device__ __forceinline__ void cp_commit() { asm volatile("cp.async.commit_group;"); }
template <int N>
__device__ __forceinline__ void cp_wait() { asm volatile("cp.async.wait_group %0;" :: "n"(N)); }

__device__ __forceinline__ void ldsm_x4(uint32_t addr, uint32_t& r0, uint32_t& r1,
                                        uint32_t& r2, uint32_t& r3) {
    asm volatile("ldmatrix.sync.aligned.m8n8.x4.shared.b16 {%0,%1,%2,%3}, [%4];"
                 : "=r"(r0), "=r"(r1), "=r"(r2), "=r"(r3) : "r"(addr));
}
__device__ __forceinline__ void ldsm_x4_t(uint32_t addr, uint32_t& r0, uint32_t& r1,
                                          uint32_t& r2, uint32_t& r3) {
    asm volatile("ldmatrix.sync.aligned.m8n8.x4.trans.shared.b16 {%0,%1,%2,%3}, [%4];"
                 : "=r"(r0), "=r"(r1), "=r"(r2), "=r"(r3) : "r"(addr));
}
__device__ __forceinline__ void mma_bf16(float* c, const uint32_t* a, uint32_t b0, uint32_t b1) {
    asm volatile(
        "mma.sync.aligned.m16n8k16.row.col.f32.bf16.bf16.f32 "
        "{%0,%1,%2,%3}, {%4,%5,%6,%7}, {%8,%9}, {%0,%1,%2,%3};"
        : "+f"(c[0]), "+f"(c[1]), "+f"(c[2]), "+f"(c[3])
        : "r"(a[0]), "r"(a[1]), "r"(a[2]), "r"(a[3]), "r"(b0), "r"(b1));
}
__device__ __forceinline__ uint32_t pack2(float x, float y) {
    __nv_bfloat162 t = __floats2bfloat162_rn(x, y);
    return *(uint32_t*)&t;
}
__device__ __forceinline__ void split2(float x, float y, uint32_t& hi, uint32_t& lo) {
    __nv_bfloat16 hx = __float2bfloat16(x);
    __nv_bfloat16 hy = __float2bfloat16(y);
    __nv_bfloat162 h2(hx, hy);
    hi = *(uint32_t*)&h2;
    lo = pack2(x - __bfloat162float(hx), y - __bfloat162float(hy));
}

// ---------------------------------------------------------------------------
// fp32 -> bf16 hi/lo split (for x, w_in, w_out)
// ---------------------------------------------------------------------------
__global__ __launch_bounds__(256)
void split_fp32(const float* __restrict__ src, __nv_bfloat16* __restrict__ hi,
                __nv_bfloat16* __restrict__ lo, int n4)
{
    const float4* s4 = (const float4*)src;
    for (int i = blockIdx.x * blockDim.x + threadIdx.x; i < n4; i += gridDim.x * blockDim.x) {
        float4 v = s4[i];
        __nv_bfloat16 h0 = __float2bfloat16(v.x);
        __nv_bfloat16 h1 = __float2bfloat16(v.y);
        __nv_bfloat16 h2 = __float2bfloat16(v.z);
        __nv_bfloat16 h3 = __float2bfloat16(v.w);
        __nv_bfloat16 l0 = __float2bfloat16(v.x - __bfloat162float(h0));
        __nv_bfloat16 l1 = __float2bfloat16(v.y - __bfloat162float(h1));
        __nv_bfloat16 l2 = __float2bfloat16(v.z - __bfloat162float(h2));
        __nv_bfloat16 l3 = __float2bfloat16(v.w - __bfloat162float(h3));
        __nv_bfloat162* hp = (__nv_bfloat162*)(hi + (size_t)i * 4);
        __nv_bfloat162* lp = (__nv_bfloat162*)(lo + (size_t)i * 4);
        hp[0] = __nv_bfloat162(h0, h1); hp[1] = __nv_bfloat162(h2, h3);
        lp[0] = __nv_bfloat162(l0, l1); lp[1] = __nv_bfloat162(l2, l3);
    }
}

// ---------------------------------------------------------------------------
// GEMM via mma.sync (3-pass hi/lo), pass-major MMA order, 2 CTAs/SM.
// MODE 0: C = acc + bias (fp32 out)
// MODE 1: QKV epilogue — split to bf16 hi/lo head-major [b][h][s][64]
// ---------------------------------------------------------------------------
#define BM 128
#define BN 128
#define BK 32
#define ROWB 80
#define TILE_SM (128 * ROWB)
#define STAGE_SM (4 * TILE_SM)
#define GEMM_SMEM (2 * STAGE_SM)

template <int MODE>
__global__ __launch_bounds__(256, 2)
void gemm_mma(const __nv_bfloat16* __restrict__ Ahi, const __nv_bfloat16* __restrict__ Alo,
              const __nv_bfloat16* __restrict__ Bhi, const __nv_bfloat16* __restrict__ Blo,
              const float* __restrict__ bias, float* __restrict__ C,
              __nv_bfloat16* __restrict__ qh, __nv_bfloat16* __restrict__ ql,
              __nv_bfloat16* __restrict__ kh, __nv_bfloat16* __restrict__ kl,
              __nv_bfloat16* __restrict__ vh, __nv_bfloat16* __restrict__ vl,
              int M, int N, int K)
{
    extern __shared__ char smem[];
    const uint32_t sbase = smem_u32(smem);
    const int tid = threadIdx.x;
    const int wid = tid >> 5;
    const int lid = tid & 31;
    const int warpM = wid & 3;
    const int warpN = wid >> 2;
    const int m0 = blockIdx.y * BM;
    const int n0 = blockIdx.x * BN;

    const int lr0 = tid >> 2;
    const int lq  = (tid & 3) * 16;

    const __nv_bfloat16* gsrc[4] = {
        Ahi + (size_t)m0 * K, Alo + (size_t)m0 * K,
        Bhi + (size_t)n0 * K, Blo + (size_t)n0 * K
    };

    float acc[2][8][4];
#pragma unroll
    for (int i = 0; i < 2; i++)
#pragma unroll
        for (int j = 0; j < 8; j++)
#pragma unroll
            for (int k = 0; k < 4; k++) acc[i][j][k] = 0.f;

    const int nch = K / BK;

    auto load_chunk = [&](int c, int buf) {
        const int k0 = c * BK;
        uint32_t st = sbase + buf * STAGE_SM;
#pragma unroll
        for (int t = 0; t < 4; t++) {
            const __nv_bfloat16* src = gsrc[t] + k0;
#pragma unroll
            for (int i = 0; i < 2; i++) {
                int r = lr0 + i * 64;
                cp_async16(st + t * TILE_SM + r * ROWB + lq,
                           (const char*)(src + (size_t)r * K) + lq);
            }
        }
        cp_commit();
    };

    auto compute_chunk = [&](int buf) {
        uint32_t st   = sbase + buf * STAGE_SM;
        uint32_t sAhi = st;
        uint32_t sAlo = st + TILE_SM;
        uint32_t sBhi = st + 2 * TILE_SM;
        uint32_t sBlo = st + 3 * TILE_SM;

#pragma unroll
        for (int ks = 0; ks < 2; ks++) {
            uint32_t ahi[2][4], alo[2][4];
            {
                int arow = warpM * 32 + (lid & 15);
                int acol = ks * 32 + (lid >> 4) * 16;
#pragma unroll
                for (int mt = 0; mt < 2; mt++) {
                    uint32_t off = (arow + mt * 16) * ROWB + acol;
                    ldsm_x4(sAhi + off, ahi[mt][0], ahi[mt][1], ahi[mt][2], ahi[mt][3]);
                    ldsm_x4(sAlo + off, alo[mt][0], alo[mt][1], alo[mt][2], alo[mt][3]);
                }
            }
            int brow_l = (lid >> 4) * 8 + (lid & 7);
            int bcol   = ks * 32 + ((lid >> 3) & 1) * 16;
#pragma unroll
            for (int nt = 0; nt < 4; nt++) {
                uint32_t off = (warpN * 64 + nt * 16 + brow_l) * ROWB + bcol;
                uint32_t bh[4], bl[4];
                ldsm_x4(sBhi + off, bh[0], bh[1], bh[2], bh[3]);
                ldsm_x4(sBlo + off, bl[0], bl[1], bl[2], bl[3]);
                // pass-major: 4 independent accumulators between dependent MMAs
#pragma unroll
                for (int mt = 0; mt < 2; mt++)
#pragma unroll
                    for (int h = 0; h < 2; h++)
                        mma_bf16(acc[mt][nt * 2 + h], ahi[mt], bh[2 * h], bh[2 * h + 1]);
#pragma unroll
                for (int mt = 0; mt < 2; mt++)
#pragma unroll
                    for (int h = 0; h < 2; h++)
                        mma_bf16(acc[mt][nt * 2 + h], ahi[mt], bl[2 * h], bl[2 * h + 1]);
#pragma unroll
                for (int mt = 0; mt < 2; mt++)
#pragma unroll
                    for (int h = 0; h < 2; h++)
                        mma_bf16(acc[mt][nt * 2 + h], alo[mt], bh[2 * h], bh[2 * h + 1]);
            }
        }
    };

    load_chunk(0, 0);
    cp_wait<0>(); __syncthreads();
    for (int c = 0; c < nch; c++) {
        if (c + 1 < nch) load_chunk(c + 1, (c + 1) & 1);
        compute_chunk(c & 1);
        cp_wait<0>(); __syncthreads();
    }

    const int rbase = m0 + warpM * 32 + (lid >> 2);
    const int cbase = n0 + warpN * 64 + 2 * (lid & 3);

    if (MODE == 0) {
#pragma unroll
        for (int mt = 0; mt < 2; mt++) {
#pragma unroll
            for (int nt = 0; nt < 8; nt++) {
                int col = cbase + nt * 8;
                float b0 = __ldg(bias + col);
                float b1 = __ldg(bias + col + 1);
                int r0 = rbase + mt * 16;
                float2 v0 = make_float2(acc[mt][nt][0] + b0, acc[mt][nt][1] + b1);
                float2 v1 = make_float2(acc[mt][nt][2] + b0, acc[mt][nt][3] + b1);
                *(float2*)&C[(size_t)r0 * N + col]       = v0;
                *(float2*)&C[(size_t)(r0 + 8) * N + col] = v1;
            }
        }
    } else {
        const int t = n0 >> 10;
        const float qs = (t == 0) ? 0.125f : 1.0f;
        __nv_bfloat16* dh = (t == 0) ? qh : (t == 1) ? kh : vh;
        __nv_bfloat16* dl = (t == 0) ? ql : (t == 1) ? kl : vl;
#pragma unroll
        for (int mt = 0; mt < 2; mt++) {
#pragma unroll
            for (int nt = 0; nt < 8; nt++) {
                int n  = cbase + nt * 8;
                float b0 = __ldg(bias + n);
                float b1 = __ldg(bias + n + 1);
                int nn = n & 1023;
                int hh = nn >> 6;
                int d  = nn & 63;
                int m  = rbase + mt * 16;
                int bb = m >> 11, ss = m & 2047;
                size_t idx = (((size_t)(bb * NHEADS + hh)) * SEQ + ss) * 64 + d;
                uint32_t hv, lv;
                split2((acc[mt][nt][0] + b0) * qs, (acc[mt][nt][1] + b1) * qs, hv, lv);
                *(uint32_t*)(dh + idx) = hv;
                *(uint32_t*)(dl + idx) = lv;
                int m2 = m + 8;
                bb = m2 >> 11; ss = m2 & 2047;
                idx = (((size_t)(bb * NHEADS + hh)) * SEQ + ss) * 64 + d;
                split2((acc[mt][nt][2] + b0) * qs, (acc[mt][nt][3] + b1) * qs, hv, lv);
                *(uint32_t*)(dh + idx) = hv;
                *(uint32_t*)(dl + idx) = lv;
            }
        }
    }
}

// ---------------------------------------------------------------------------
// Tensor-core flash attention (mma.sync, 3-pass hi/lo, FA2 fragment softmax).
// 128 threads (4 warps x 16 q-rows), q-tile 64, k-tile 64.
// Pass-major MMA order with nt-pairing (4 independent accumulators).
// ---------------------------------------------------------------------------
#define AROWB 144
#define ATILE (64 * AROWB)
#define AQ_HI 0
#define AQ_LO ATILE
#define ASTG  (2 * ATILE)
#define ASTGSZ (4 * ATILE)
#define ATT_SMEM (ASTG + 2 * ASTGSZ)   // 92160

__global__ __launch_bounds__(128)
void attn_mma(const __nv_bfloat16* __restrict__ qh, const __nv_bfloat16* __restrict__ ql,
              const __nv_bfloat16* __restrict__ kh, const __nv_bfloat16* __restrict__ kl,
              const __nv_bfloat16* __restrict__ vh, const __nv_bfloat16* __restrict__ vl,
              __nv_bfloat16* __restrict__ ahi, __nv_bfloat16* __restrict__ alo,
              const int* __restrict__ causal_flag)
{
    extern __shared__ char smem[];
    const uint32_t sbase = smem_u32(smem);
    const int tid = threadIdx.x;
    const int wid = tid >> 5;
    const int lid = tid & 31;
    const int iq  = blockIdx.x;
    const int bh  = blockIdx.y;
    const int q0  = iq * 64;
    const int causal = *causal_flag;

    const size_t headbase = (size_t)bh * SEQ * 64;

    auto load_tile = [&](uint32_t sdst, const __nv_bfloat16* g) {
        int row = tid >> 1;
        const char* gr = (const char*)(g + (size_t)row * 64);
        uint32_t sr = sdst + row * AROWB;
#pragma unroll
        for (int i = 0; i < 4; i++) {
            int c = (tid & 1) * 4 + i;
            cp_async16(sr + c * 16, gr + c * 16);
        }
    };

    load_tile(sbase + AQ_HI, qh + headbase + (size_t)q0 * 64);
    load_tile(sbase + AQ_LO, ql + headbase + (size_t)q0 * 64);

    auto load_kv = [&](int jk, int buf) {
        size_t off = headbase + (size_t)jk * 64 * 64;
        uint32_t st = sbase + ASTG + buf * ASTGSZ;
        load_tile(st,             kh + off);
        load_tile(st + ATILE,     kl + off);
        load_tile(st + 2 * ATILE, vh + off);
        load_tile(st + 3 * ATILE, vl + off);
        cp_commit();
    };

    load_kv(0, 0);
    cp_wait<0>(); __syncthreads();

    uint32_t qfh[4][4], qfl[4][4];
    {
        int arow = wid * 16 + (lid & 15);
        int acol = (lid >> 4) * 16;
#pragma unroll
        for (int ks = 0; ks < 4; ks++) {
            uint32_t off = arow * AROWB + ks * 32 + acol;
            ldsm_x4(sbase + AQ_HI + off, qfh[ks][0], qfh[ks][1], qfh[ks][2], qfh[ks][3]);
            ldsm_x4(sbase + AQ_LO + off, qfl[ks][0], qfl[ks][1], qfl[ks][2], qfl[ks][3]);
        }
    }

    float Oacc[8][4];
#pragma unroll
    for (int j = 0; j < 8; j++)
#pragma unroll
        for (int c = 0; c < 4; c++) Oacc[j][c] = 0.f;
    float m0 = -INFINITY, m1 = -INFINITY, l0 = 0.f, l1 = 0.f;

    const int ntiles = causal ? (iq + 1) : (SEQ / 64);

    for (int jk = 0; jk < ntiles; jk++) {
        if (jk + 1 < ntiles) load_kv(jk + 1, (jk + 1) & 1);

        uint32_t st = sbase + ASTG + (jk & 1) * ASTGSZ;
        uint32_t sKh = st, sKl = st + ATILE, sVh = st + 2 * ATILE, sVl = st + 3 * ATILE;

        // ---- S = Q @ K^T (3-pass, nt-paired pass-major) ----
        float S[8][4];
#pragma unroll
        for (int j = 0; j < 8; j++)
#pragma unroll
            for (int c = 0; c < 4; c++) S[j][c] = 0.f;
        {
            int brow = (lid >> 4) * 8 + (lid & 7);
            int bcx  = ((lid >> 3) & 1) * 16;
#pragma unroll
            for (int ks = 0; ks < 4; ks++) {
#pragma unroll
                for (int nt = 0; nt < 4; nt += 2) {
                    uint32_t off0 = (nt * 16 + brow) * AROWB + ks * 32 + bcx;
                    uint32_t off1 = ((nt + 1) * 16 + brow) * AROWB + ks * 32 + bcx;
                    uint32_t bh0[4], bl0[4], bh1[4], bl1[4];
                    ldsm_x4(sKh + off0, bh0[0], bh0[1], bh0[2], bh0[3]);
                    ldsm_x4(sKl + off0, bl0[0], bl0[1], bl0[2], bl0[3]);
                    ldsm_x4(sKh + off1, bh1[0], bh1[1], bh1[2], bh1[3]);
                    ldsm_x4(sKl + off1, bl1[0], bl1[1], bl1[2], bl1[3]);
#pragma unroll
                    for (int h = 0; h < 2; h++) {
                        mma_bf16(S[nt * 2 + h],       qfh[ks], bh0[2 * h], bh0[2 * h + 1]);
                        mma_bf16(S[(nt + 1) * 2 + h], qfh[ks], bh1[2 * h], bh1[2 * h + 1]);
                    }
#pragma unroll
                    for (int h = 0; h < 2; h++) {
                        mma_bf16(S[nt * 2 + h],       qfh[ks], bl0[2 * h], bl0[2 * h + 1]);
                        mma_bf16(S[(nt + 1) * 2 + h], qfh[ks], bl1[2 * h], bl1[2 * h + 1]);
                    }
#pragma unroll
                    for (int h = 0; h < 2; h++) {
                        mma_bf16(S[nt * 2 + h],       qfl[ks], bh0[2 * h], bh0[2 * h + 1]);
                        mma_bf16(S[(nt + 1) * 2 + h], qfl[ks], bh1[2 * h], bh1[2 * h + 1]);
                    }
                }
            }
        }

        // ---- causal mask on diagonal tile ----
        const int k0 = jk * 64;
        if (causal && jk == iq) {
            int rg0 = q0 + wid * 16 + (lid >> 2);
#pragma unroll
            for (int j = 0; j < 8; j++) {
                int cg = k0 + j * 8 + 2 * (lid & 3);
#pragma unroll
                for (int c = 0; c < 4; c++) {
                    int rg = rg0 + (c >> 1) * 8;
                    if (cg + (c & 1) > rg) S[j][c] = -INFINITY;
                }
            }
        }

        // ---- online softmax ----
        float mx0 = -INFINITY, mx1 = -INFINITY;
#pragma unroll
        for (int j = 0; j < 8; j++) {
            mx0 = fmaxf(mx0, fmaxf(S[j][0], S[j][1]));
            mx1 = fmaxf(mx1, fmaxf(S[j][2], S[j][3]));
        }
        mx0 = fmaxf(mx0, __shfl_xor_sync(0xffffffff, mx0, 1));
        mx0 = fmaxf(mx0, __shfl_xor_sync(0xffffffff, mx0, 2));
        mx1 = fmaxf(mx1, __shfl_xor_sync(0xffffffff, mx1, 1));
        mx1 = fmaxf(mx1, __shfl_xor_sync(0xffffffff, mx1, 2));

        float mn0 = fmaxf(m0, mx0), mn1 = fmaxf(m1, mx1);
        float sc0 = __expf(m0 - mn0), sc1 = __expf(m1 - mn1);

        uint32_t pfh[4][4], pfl[4][4];
        float sum0 = 0.f, sum1 = 0.f;
#pragma unroll
        for (int ks = 0; ks < 4; ks++) {
#pragma unroll
            for (int half = 0; half < 2; half++) {
                int j = 2 * ks + half;
                float p0 = __expf(S[j][0] - mn0);
                float p1 = __expf(S[j][1] - mn0);
                float p2 = __expf(S[j][2] - mn1);
                float p3 = __expf(S[j][3] - mn1);
                sum0 += p0 + p1;
                sum1 += p2 + p3;
                split2(p0, p1, pfh[ks][half * 2 + 0], pfl[ks][half * 2 + 0]);
                split2(p2, p3, pfh[ks][half * 2 + 1], pfl[ks][half * 2 + 1]);
            }
        }
        sum0 += __shfl_xor_sync(0xffffffff, sum0, 1);
        sum0 += __shfl_xor_sync(0xffffffff, sum0, 2);
        sum1 += __shfl_xor_sync(0xffffffff, sum1, 1);
        sum1 += __shfl_xor_sync(0xffffffff, sum1, 2);

        l0 = l0 * sc0 + sum0;
        l1 = l1 * sc1 + sum1;
        m0 = mn0; m1 = mn1;

#pragma unroll
        for (int j = 0; j < 8; j++) {
            Oacc[j][0] *= sc0; Oacc[j][1] *= sc0;
            Oacc[j][2] *= sc1; Oacc[j][3] *= sc1;
        }

        // ---- O += P @ V (3-pass, nt-paired pass-major, V via ldmatrix.trans) ----
        {
            int vr  = ((lid >> 3) & 1) * 8 + (lid & 7);
            int vcx = (lid >> 4) * 16;
#pragma unroll
            for (int ks = 0; ks < 4; ks++) {
#pragma unroll
                for (int nt = 0; nt < 4; nt += 2) {
                    uint32_t off0 = (ks * 16 + vr) * AROWB + nt * 32 + vcx;
                    uint32_t off1 = (ks * 16 + vr) * AROWB + (nt + 1) * 32 + vcx;
                    uint32_t vh0[4], vl0[4], vh1[4], vl1[4];
                    ldsm_x4_t(sVh + off0, vh0[0], vh0[1], vh0[2], vh0[3]);
                    ldsm_x4_t(sVl + off0, vl0[0], vl0[1], vl0[2], vl0[3]);
                    ldsm_x4_t(sVh + off1, vh1[0], vh1[1], vh1[2], vh1[3]);
                    ldsm_x4_t(sVl + off1, vl1[0], vl1[1], vl1[2], vl1[3]);
#pragma unroll
                    for (int h = 0; h < 2; h++) {
                        mma_bf16(Oacc[nt * 2 + h],       pfh[ks], vh0[2 * h], vh0[2 * h + 1]);
                        mma_bf16(Oacc[(nt + 1) * 2 + h], pfh[ks], vh1[2 * h], vh1[2 * h + 1]);
                    }
#pragma unroll
                    for (int h = 0; h < 2; h++) {
                        mma_bf16(Oacc[nt * 2 + h],       pfh[ks], vl0[2 * h], vl0[2 * h + 1]);
                        mma_bf16(Oacc[(nt + 1) * 2 + h], pfh[ks], vl1[2 * h], vl1[2 * h + 1]);
                    }
#pragma unroll
                    for (int h = 0; h < 2; h++) {
                        mma_bf16(Oacc[nt * 2 + h],       pfl[ks], vh0[2 * h], vh0[2 * h + 1]);
                        mma_bf16(Oacc[(nt + 1) * 2 + h], pfl[ks], vh1[2 * h], vh1[2 * h + 1]);
                    }
                }
            }
        }
        cp_wait<0>(); __syncthreads();
    }

    // ---- epilogue: fused fp32->bf16 hi/lo split ----
    const int b = bh >> 4, h = bh & 15;
    const int row0 = q0 + wid * 16 + (lid >> 2);
    float inv0 = 1.f / l0, inv1 = 1.f / l1;
#pragma unroll
    for (int j = 0; j < 8; j++) {
        int col = h * 64 + j * 8 + 2 * (lid & 3);
        size_t idx0 = (size_t)(b * SEQ + row0) * DEMB + col;
        size_t idx1 = (size_t)(b * SEQ + row0 + 8) * DEMB + col;
        uint32_t hv, lv;
        split2(Oacc[j][0] * inv0, Oacc[j][1] * inv0, hv, lv);
        *(uint32_t*)(ahi + idx0) = hv;
        *(uint32_t*)(alo + idx0) = lv;
        split2(Oacc[j][2] * inv1, Oacc[j][3] * inv1, hv, lv);
        *(uint32_t*)(ahi + idx1) = hv;
        *(uint32_t*)(alo + idx1) = lv;
    }
}

// ---------------------------------------------------------------------------
// Launch
// ---------------------------------------------------------------------------
extern "C" void kernel_launch(void* const* d_in, const int* in_sizes, int n_in,
                              void* d_out, int out_size)
{
    (void)in_sizes; (void)n_in; (void)out_size;
    const float* x      = (const float*)d_in[0];
    const float* w_in   = (const float*)d_in[1];
    const float* b_in   = (const float*)d_in[2];
    const float* w_out  = (const float*)d_in[3];
    const float* b_out  = (const float*)d_in[4];
    const int*   causal = (const int*)  d_in[5];
    float* out = (float*)d_out;

    __nv_bfloat16 *xhi, *xlo, *wihi, *wilo, *wohi, *wolo;
    __nv_bfloat16 *qh, *ql, *kh, *kl, *vh, *vl, *ahi, *alo;
    cudaGetSymbolAddress((void**)&xhi, g_xhi);
    cudaGetSymbolAddress((void**)&xlo, g_xlo);
    cudaGetSymbolAddress((void**)&wihi, g_wihi);
    cudaGetSymbolAddress((void**)&wilo, g_wilo);
    cudaGetSymbolAddress((void**)&wohi, g_wohi);
    cudaGetSymbolAddress((void**)&wolo, g_wolo);
    cudaGetSymbolAddress((void**)&qh, g_qh);
    cudaGetSymbolAddress((void**)&ql, g_ql);
    cudaGetSymbolAddress((void**)&kh, g_kh);
    cudaGetSymbolAddress((void**)&kl, g_kl);
    cudaGetSymbolAddress((void**)&vh, g_vh);
    cudaGetSymbolAddress((void**)&vl, g_vl);
    cudaGetSymbolAddress((void**)&ahi, g_ahi);
    cudaGetSymbolAddress((void**)&alo, g_alo);

    cudaFuncSetAttribute(gemm_mma<0>, cudaFuncAttributeMaxDynamicSharedMemorySize, GEMM_SMEM);
    cudaFuncSetAttribute(gemm_mma<1>, cudaFuncAttributeMaxDynamicSharedMemorySize, GEMM_SMEM);
    cudaFuncSetAttribute(attn_mma, cudaFuncAttributeMaxDynamicSharedMemorySize, ATT_SMEM);

    // 1) split inputs
    split_fp32<<<1024, 256>>>(x, xhi, xlo, (MROWS * DEMB) / 4);
    split_fp32<<<512, 256>>>(w_in, wihi, wilo, (QKV_N * DEMB) / 4);
    split_fp32<<<256, 256>>>(w_out, wohi, wolo, (DEMB * DEMB) / 4);

    // 2) QKV projection, fused head-major hi/lo split epilogue
    {
        dim3 grid(QKV_N / BN, MROWS / BM);
        gemm_mma<1><<<grid, 256, GEMM_SMEM>>>(xhi, xlo, wihi, wilo, b_in, nullptr,
                                              qh, ql, kh, kl, vh, vl,
                                              MROWS, QKV_N, DEMB);
    }

    // 3) attention, fused hi/lo split epilogue
    {
        dim3 grid(SEQ / 64, BATCH * NHEADS);
        attn_mma<<<grid, 128, ATT_SMEM>>>(qh, ql, kh, kl, vh, vl, ahi, alo, causal);
    }

    // 4) output projection (fp32 + bias)
    {
        dim3 grid(DEMB / BN, MROWS / BM);
        gemm_mma<0><<<grid, 256, GEMM_SMEM>>>(ahi, alo, wohi, wolo, b_out, out,
                                              nullptr, nullptr, nullptr, nullptr, nullptr, nullptr,
                                              MROWS, DEMB, DEMB);
    }
}